// round 13
// baseline (speedup 1.0000x reference)
#include <cuda_runtime.h>
#include <cuda_fp16.h>

#define SEQ 4096
#define DMODEL 1024
#define NHEADS 16
#define HDIM 64
#define QKV_N 3072

// Scratch (static device arrays — no allocation)
__device__ __half g_qkv_h[SEQ * QKV_N];   // q|k|v fp16
__device__ __half g_ctx_h[SEQ * DMODEL];  // ctx fp16
__device__ __half g_x_h[SEQ * DMODEL];            // x fp16
__device__ __half g_wqkvT_h[QKV_N * DMODEL];      // w_qkv^T [N][K] fp16
__device__ __half g_woutT_h[DMODEL * DMODEL];     // w_out^T [N][K] fp16

// ---------------------------------------------------------------------------
// helpers
// ---------------------------------------------------------------------------
__device__ __forceinline__ void mma_f16(float c[4], const unsigned a[4], const unsigned b[2]) {
    asm volatile(
        "mma.sync.aligned.m16n8k16.row.col.f32.f16.f16.f32 "
        "{%0,%1,%2,%3},{%4,%5,%6,%7},{%8,%9},{%0,%1,%2,%3};"
        : "+f"(c[0]), "+f"(c[1]), "+f"(c[2]), "+f"(c[3])
        : "r"(a[0]), "r"(a[1]), "r"(a[2]), "r"(a[3]), "r"(b[0]), "r"(b[1]));
}

__device__ __forceinline__ void ldsm_x4(unsigned r[4], unsigned addr) {
    asm volatile("ldmatrix.sync.aligned.m8n8.x4.shared.b16 {%0,%1,%2,%3}, [%4];"
                 : "=r"(r[0]), "=r"(r[1]), "=r"(r[2]), "=r"(r[3]) : "r"(addr));
}

__device__ __forceinline__ float ex2(float x) {
    float y;
    asm("ex2.approx.f32 %0, %1;" : "=f"(y) : "f"(x));
    return y;
}

__device__ __forceinline__ void cp16(void* dst_smem, const void* src_gmem) {
    unsigned d = (unsigned)__cvta_generic_to_shared(dst_smem);
    asm volatile("cp.async.cg.shared.global [%0], [%1], 16;" :: "r"(d), "l"(src_gmem));
}
#define CP_COMMIT() asm volatile("cp.async.commit_group;")
#define CP_WAIT0()  asm volatile("cp.async.wait_group 0;")

// fp32 -> fp16 elementwise (float4 granularity)
__global__ void f2h_kernel(const float* __restrict__ in, __half* __restrict__ out, int n4) {
    int i = blockIdx.x * blockDim.x + threadIdx.x;
    if (i >= n4) return;
    float4 v = ((const float4*)in)[i];
    ((__half2*)out)[2 * i]     = __floats2half2_rn(v.x, v.y);
    ((__half2*)out)[2 * i + 1] = __floats2half2_rn(v.z, v.w);
}

// out[C][R] (fp16) = in[R][C]^T
__global__ void transpose_h_kernel(const float* __restrict__ in,
                                   __half* __restrict__ out, int R, int C) {
    __shared__ float t[32][33];
    int c0 = blockIdx.x * 32, r0 = blockIdx.y * 32;
    int tx = threadIdx.x, ty = threadIdx.y;
    #pragma unroll
    for (int i = 0; i < 4; i++)
        t[ty + i * 8][tx] = in[(size_t)(r0 + ty + i * 8) * C + c0 + tx];
    __syncthreads();
    #pragma unroll
    for (int i = 0; i < 4; i++)
        out[(size_t)(c0 + ty + i * 8) * R + r0 + tx] = __float2half(t[tx][ty + i * 8]);
}

// ---------------------------------------------------------------------------
// FP16 tensor-core GEMM, 128x256 CTA tile, 64x64 warp tiles (2m x 4n).
// C[M,N] = A[M,K] @ BT[N,K]^T + bias. BK=32. 256 threads = 8 warps.
// ldmatrix fragment loads; 16 LDSM : 64 HMMA per warp per k-tile.
// ---------------------------------------------------------------------------
#define PHG 40   // smem pitch in halves; 20 words: 20r mod 32 spans all banks

__global__ __launch_bounds__(256, 1) void gemm_h_kernel(
    const __half* __restrict__ A, const __half* __restrict__ BT,
    const float* __restrict__ bias, void* __restrict__ Cout,
    int M, int N, int K, int half_out) {
    __shared__ __half As[128 * PHG];
    __shared__ __half Bs[256 * PHG];

    int tid = threadIdx.x;
    int wid = tid >> 5, lane = tid & 31;
    int g = lane >> 2, tig = lane & 3;
    int warp_m = wid >> 2, warp_n = wid & 3;
    int bm = blockIdx.y * 128, bn = blockIdx.x * 256;

    // loaders: A 128 rows x 32 halves (2 threads/row); B 256 rows x 32 (1 thread/row)
    int lr = tid >> 1, lc = (tid & 1) * 16;
    const __half* Agp = A + (size_t)(bm + lr) * K + lc;
    const __half* Bgp = BT + (size_t)(bn + tid) * K;

    // ldmatrix lane addressing
    int lm = lane >> 3, lrw = lane & 7;
    unsigned a_addr[4], b_addr[4];
    #pragma unroll
    for (int mc = 0; mc < 4; mc++)
        a_addr[mc] = (unsigned)__cvta_generic_to_shared(
            &As[(warp_m * 64 + mc * 16 + (lm & 1) * 8 + lrw) * PHG + (lm >> 1) * 8]);
    #pragma unroll
    for (int j = 0; j < 4; j++)
        b_addr[j] = (unsigned)__cvta_generic_to_shared(
            &Bs[(warp_n * 64 + j * 16 + (lm >> 1) * 8 + lrw) * PHG + (lm & 1) * 8]);

    float acc[4][8][4];
    #pragma unroll
    for (int mc = 0; mc < 4; mc++)
        #pragma unroll
        for (int nc = 0; nc < 8; nc++)
            #pragma unroll
            for (int i = 0; i < 4; i++) acc[mc][nc][i] = 0.0f;

    for (int k0 = 0; k0 < K; k0 += 32) {
        __syncthreads();
        *(uint4*)&As[lr * PHG + lc]      = *(const uint4*)(Agp + k0);
        *(uint4*)&As[lr * PHG + lc + 8]  = *(const uint4*)(Agp + k0 + 8);
        *(uint4*)&Bs[tid * PHG]          = *(const uint4*)(Bgp + k0);
        *(uint4*)&Bs[tid * PHG + 8]      = *(const uint4*)(Bgp + k0 + 8);
        *(uint4*)&Bs[tid * PHG + 16]     = *(const uint4*)(Bgp + k0 + 16);
        *(uint4*)&Bs[tid * PHG + 24]     = *(const uint4*)(Bgp + k0 + 24);
        __syncthreads();

        #pragma unroll
        for (int kc = 0; kc < 2; kc++) {
            unsigned a[4][4];
            #pragma unroll
            for (int mc = 0; mc < 4; mc++) ldsm_x4(a[mc], a_addr[mc] + kc * 32);
            #pragma unroll
            for (int j = 0; j < 4; j++) {
                unsigned bb[4];
                ldsm_x4(bb, b_addr[j] + kc * 32);
                #pragma unroll
                for (int mc = 0; mc < 4; mc++) {
                    mma_f16(acc[mc][2 * j],     a[mc], bb);
                    mma_f16(acc[mc][2 * j + 1], a[mc], bb + 2);
                }
            }
        }
    }

    // Epilogue
    #pragma unroll
    for (int nc = 0; nc < 8; nc++) {
        int col = bn + warp_n * 64 + nc * 8 + 2 * tig;
        float bv0 = bias[col], bv1 = bias[col + 1];
        #pragma unroll
        for (int mc = 0; mc < 4; mc++) {
            int row = bm + warp_m * 64 + mc * 16 + g;
            float v00 = acc[mc][nc][0] + bv0, v01 = acc[mc][nc][1] + bv1;
            float v10 = acc[mc][nc][2] + bv0, v11 = acc[mc][nc][3] + bv1;
            if (half_out) {
                __half* Ch = (__half*)Cout;
                *(__half2*)&Ch[(size_t)row * N + col]       = __floats2half2_rn(v00, v01);
                *(__half2*)&Ch[(size_t)(row + 8) * N + col] = __floats2half2_rn(v10, v11);
            } else {
                float* Cf = (float*)Cout;
                *(float2*)&Cf[(size_t)row * N + col]       = make_float2(v00, v01);
                *(float2*)&Cf[(size_t)(row + 8) * N + col] = make_float2(v10, v11);
            }
        }
    }
}

// ---------------------------------------------------------------------------
// Flash attention (causal), fp16 m16n8k16 mma, ldmatrix fragment loads,
// exp2-domain softmax. One CTA per (q-block 64, head). 128 threads = 4 warps.
// (unchanged from R12 — known good)
// ---------------------------------------------------------------------------
#define PW 36
#define ROWB 144   // bytes per tile row (36 words)
#define SCALE2 0.18033688011112042f   // 0.125 * log2(e)

__global__ __launch_bounds__(128) void attn_h_kernel() {
    extern __shared__ unsigned sm[];
    unsigned* Ps = sm;                 // [64 rows][36 words] (kpos pairs)
    unsigned* Ks = Ps + 64 * PW;       // [2][64 kpos][36 words] (hd halves)
    unsigned* Vs = Ks + 2 * 64 * PW;   // [2][64 hd][36 words] (kpos pairs)

    int qb = gridDim.x - 1 - blockIdx.x;  // longest CTAs first
    int h  = blockIdx.y;
    int tid = threadIdx.x;
    int wid = tid >> 5, lane = tid & 31;
    int g = lane >> 2, tig = lane & 3;
    int row0 = wid * 16;

    const int k_off = DMODEL + h * HDIM;
    const int v_off = 2 * DMODEL + h * HDIM;

    unsigned smb = (unsigned)__cvta_generic_to_shared(sm);
    unsigned ps_b = smb;
    unsigned ks_b = smb + 64 * ROWB;
    unsigned vs_b = ks_b + 2 * 64 * ROWB;

    int lm = lane >> 3, lrw = lane & 7;
    unsigned apat = (unsigned)((row0 + (lm & 1) * 8 + lrw) * ROWB + (lm >> 1) * 16);
    unsigned bpat[4];
    #pragma unroll
    for (int j = 0; j < 4; j++)
        bpat[j] = (unsigned)((j * 16 + (lm >> 1) * 8 + lrw) * ROWB + (lm & 1) * 16);

    auto cp_k = [&](int jb, int buf) {
        char* Kd = (char*)(Ks + buf * 64 * PW);
        #pragma unroll
        for (int i = 0; i < 4; i++) {
            int linear = tid + i * 128;
            int r  = linear >> 3;
            int c8 = (linear & 7) * 8;
            cp16(Kd + r * ROWB + c8 * 2,
                 &g_qkv_h[(size_t)(jb * 64 + r) * QKV_N + k_off + c8]);
        }
    };

    int vc0 = wid * 16, vp = lane;
    uint4 vr[4];
    auto v_ldg = [&](int jb) {
        const __half* p0 = &g_qkv_h[(size_t)(jb * 64 + 2 * vp) * QKV_N + v_off + vc0];
        vr[0] = *(const uint4*)p0;
        vr[1] = *(const uint4*)(p0 + 8);
        vr[2] = *(const uint4*)(p0 + QKV_N);
        vr[3] = *(const uint4*)(p0 + QKV_N + 8);
    };
    auto v_sts = [&](int buf) {
        unsigned* Vd = Vs + buf * 64 * PW;
        const __half* r0lo = (const __half*)&vr[0];
        const __half* r0hi = (const __half*)&vr[1];
        const __half* r1lo = (const __half*)&vr[2];
        const __half* r1hi = (const __half*)&vr[3];
        #pragma unroll
        for (int j = 0; j < 8; j++) {
            __half2 w0 = __halves2half2(r0lo[j], r1lo[j]);
            Vd[(vc0 + j) * PW + vp] = *(unsigned*)&w0;
            __half2 w1 = __halves2half2(r0hi[j], r1hi[j]);
            Vd[(vc0 + 8 + j) * PW + vp] = *(unsigned*)&w1;
        }
    };

    cp_k(0, 0);
    CP_COMMIT();
    v_ldg(0);

    unsigned qf[4][4];
    {
        const __half* Qb = g_qkv_h + (size_t)(qb * 64) * QKV_N + h * HDIM;
        #pragma unroll
        for (int kc = 0; kc < 4; kc++) {
            qf[kc][0] = *(const unsigned*)&Qb[(size_t)(row0 + g) * QKV_N + kc * 16 + 2 * tig];
            qf[kc][1] = *(const unsigned*)&Qb[(size_t)(row0 + g + 8) * QKV_N + kc * 16 + 2 * tig];
            qf[kc][2] = *(const unsigned*)&Qb[(size_t)(row0 + g) * QKV_N + kc * 16 + 2 * tig + 8];
            qf[kc][3] = *(const unsigned*)&Qb[(size_t)(row0 + g + 8) * QKV_N + kc * 16 + 2 * tig + 8];
        }
    }
    v_sts(0);

    float o[8][4];
    #pragma unroll
    for (int nc = 0; nc < 8; nc++)
        #pragma unroll
        for (int i = 0; i < 4; i++) o[nc][i] = 0.0f;
    float m0 = -1e30f, m1 = -1e30f, l0 = 0.0f, l1 = 0.0f;

    for (int jb = 0; jb <= qb; jb++) {
        int buf = jb & 1;
        CP_WAIT0();
        __syncthreads();

        if (jb < qb) {
            cp_k(jb + 1, buf ^ 1);
            CP_COMMIT();
            v_ldg(jb + 1);
        }

        unsigned kc_b = ks_b + buf * 64 * ROWB;
        unsigned vc_b = vs_b + buf * 64 * ROWB;

        float s[8][4];
        #pragma unroll
        for (int nc = 0; nc < 8; nc++)
            #pragma unroll
            for (int i = 0; i < 4; i++) s[nc][i] = 0.0f;

        #pragma unroll
        for (int kc = 0; kc < 4; kc++) {
            #pragma unroll
            for (int j = 0; j < 4; j++) {
                unsigned bb[4];
                ldsm_x4(bb, kc_b + bpat[j] + kc * 32);
                mma_f16(s[2 * j],     qf[kc], bb);
                mma_f16(s[2 * j + 1], qf[kc], bb + 2);
            }
        }

        #pragma unroll
        for (int nc = 0; nc < 8; nc++)
            #pragma unroll
            for (int i = 0; i < 4; i++) s[nc][i] *= SCALE2;

        if (jb == qb) {
            int r_lo = row0 + g, r_hi = row0 + g + 8;
            #pragma unroll
            for (int nc = 0; nc < 8; nc++) {
                int c0 = nc * 8 + 2 * tig, c1 = c0 + 1;
                if (c0 > r_lo) s[nc][0] = -1e30f;
                if (c1 > r_lo) s[nc][1] = -1e30f;
                if (c0 > r_hi) s[nc][2] = -1e30f;
                if (c1 > r_hi) s[nc][3] = -1e30f;
            }
        }

        if (jb < qb) v_sts(buf ^ 1);

        float mx0 = -1e30f, mx1 = -1e30f;
        #pragma unroll
        for (int nc = 0; nc < 8; nc++) {
            mx0 = fmaxf(mx0, fmaxf(s[nc][0], s[nc][1]));
            mx1 = fmaxf(mx1, fmaxf(s[nc][2], s[nc][3]));
        }
        mx0 = fmaxf(mx0, __shfl_xor_sync(0xffffffffu, mx0, 1));
        mx0 = fmaxf(mx0, __shfl_xor_sync(0xffffffffu, mx0, 2));
        mx1 = fmaxf(mx1, __shfl_xor_sync(0xffffffffu, mx1, 1));
        mx1 = fmaxf(mx1, __shfl_xor_sync(0xffffffffu, mx1, 2));

        float mn0 = fmaxf(m0, mx0), mn1 = fmaxf(m1, mx1);
        float al0 = ex2(m0 - mn0), al1 = ex2(m1 - mn1);

        float rs0 = 0.0f, rs1 = 0.0f;
        #pragma unroll
        for (int nc = 0; nc < 8; nc++) {
            float p0 = ex2(s[nc][0] - mn0);
            float p1 = ex2(s[nc][1] - mn0);
            float p2 = ex2(s[nc][2] - mn1);
            float p3 = ex2(s[nc][3] - mn1);
            rs0 += p0 + p1;
            rs1 += p2 + p3;
            __half2 lo = __floats2half2_rn(p0, p1);
            __half2 hi = __floats2half2_rn(p2, p3);
            Ps[(row0 + g) * PW + nc * 4 + tig]     = *(unsigned*)&lo;
            Ps[(row0 + g + 8) * PW + nc * 4 + tig] = *(unsigned*)&hi;
        }
        rs0 += __shfl_xor_sync(0xffffffffu, rs0, 1);
        rs0 += __shfl_xor_sync(0xffffffffu, rs0, 2);
        rs1 += __shfl_xor_sync(0xffffffffu, rs1, 1);
        rs1 += __shfl_xor_sync(0xffffffffu, rs1, 2);

        l0 = l0 * al0 + rs0;
        l1 = l1 * al1 + rs1;
        m0 = mn0;
        m1 = mn1;
        #pragma unroll
        for (int nc = 0; nc < 8; nc++) {
            o[nc][0] *= al0; o[nc][1] *= al0;
            o[nc][2] *= al1; o[nc][3] *= al1;
        }
        __syncwarp();

        #pragma unroll
        for (int kc = 0; kc < 4; kc++) {
            unsigned a[4];
            ldsm_x4(a, ps_b + apat + kc * 32);
            #pragma unroll
            for (int j = 0; j < 4; j++) {
                unsigned bb[4];
                ldsm_x4(bb, vc_b + bpat[j] + kc * 32);
                mma_f16(o[2 * j],     a, bb);
                mma_f16(o[2 * j + 1], a, bb + 2);
            }
        }
    }

    float inv0 = 1.0f / l0, inv1 = 1.0f / l1;
    #pragma unroll
    for (int nc = 0; nc < 8; nc++) {
        int col = h * HDIM + nc * 8 + 2 * tig;
        int r_lo = qb * 64 + row0 + g;
        __half2 lo = __floats2half2_rn(o[nc][0] * inv0, o[nc][1] * inv0);
        __half2 hi = __floats2half2_rn(o[nc][2] * inv1, o[nc][3] * inv1);
        *(__half2*)&g_ctx_h[(size_t)r_lo * DMODEL + col]       = lo;
        *(__half2*)&g_ctx_h[(size_t)(r_lo + 8) * DMODEL + col] = hi;
    }
}

// ---------------------------------------------------------------------------
extern "C" void kernel_launch(void* const* d_in, const int* in_sizes, int n_in,
                              void* d_out, int out_size) {
    (void)in_sizes; (void)n_in; (void)out_size;
    const float* x     = (const float*)d_in[0];
    const float* w_qkv = (const float*)d_in[1];
    const float* b_qkv = (const float*)d_in[2];
    const float* w_out = (const float*)d_in[3];
    const float* b_out = (const float*)d_in[4];
    float* out = (float*)d_out;

    __half *qkv_ptr, *ctx_ptr, *xh_ptr, *wqkvT_ptr, *woutT_ptr;
    cudaGetSymbolAddress((void**)&qkv_ptr,   g_qkv_h);
    cudaGetSymbolAddress((void**)&ctx_ptr,   g_ctx_h);
    cudaGetSymbolAddress((void**)&xh_ptr,    g_x_h);
    cudaGetSymbolAddress((void**)&wqkvT_ptr, g_wqkvT_h);
    cudaGetSymbolAddress((void**)&woutT_ptr, g_woutT_h);

    const int ATTN_SMEM = 5 * 64 * PW * (int)sizeof(unsigned);   // 46080
    static bool attr_set = false;
    if (!attr_set) {
        cudaFuncSetAttribute(attn_h_kernel,
                             cudaFuncAttributeMaxDynamicSharedMemorySize, ATTN_SMEM);
        attr_set = true;
    }

    // 0) Convert inputs: x -> fp16; weights -> transposed fp16 [N][K]
    f2h_kernel<<<(SEQ * DMODEL / 4 + 255) / 256, 256>>>(x, xh_ptr, SEQ * DMODEL / 4);
    transpose_h_kernel<<<dim3(QKV_N / 32, DMODEL / 32), dim3(32, 8)>>>(
        w_qkv, wqkvT_ptr, DMODEL, QKV_N);
    transpose_h_kernel<<<dim3(DMODEL / 32, DMODEL / 32), dim3(32, 8)>>>(
        w_out, woutT_ptr, DMODEL, DMODEL);

    // 1) QKV projection (fp16 out)
    gemm_h_kernel<<<dim3(QKV_N / 256, SEQ / 128), 256>>>(
        xh_ptr, wqkvT_ptr, b_qkv, qkv_ptr, SEQ, QKV_N, DMODEL, 1);

    // 2) Causal attention
    attn_h_kernel<<<dim3(SEQ / 64, NHEADS), 128, ATTN_SMEM>>>();

    // 3) Output projection (fp32 out)
    gemm_h_kernel<<<dim3(DMODEL / 256, SEQ / 128), 256>>>(
        ctx_ptr, woutT_ptr, b_out, out, SEQ, DMODEL, DMODEL, 0);
}

// round 14
// speedup vs baseline: 1.1126x; 1.1126x over previous
#include <cuda_runtime.h>
#include <cuda_fp16.h>

#define SEQ 4096
#define DMODEL 1024
#define NHEADS 16
#define HDIM 64
#define QKV_N 3072

// Scratch (static device arrays — no allocation)
__device__ __half g_qkv_h[SEQ * QKV_N];   // q|k|v fp16
__device__ __half g_ctx_h[SEQ * DMODEL];  // ctx fp16
__device__ __half g_x_h[SEQ * DMODEL];            // x fp16
__device__ __half g_wqkvT_h[QKV_N * DMODEL];      // w_qkv^T [N][K] fp16
__device__ __half g_woutT_h[DMODEL * DMODEL];     // w_out^T [N][K] fp16

// ---------------------------------------------------------------------------
// helpers
// ---------------------------------------------------------------------------
__device__ __forceinline__ void mma_f16(float c[4], const unsigned a[4], const unsigned b[2]) {
    asm volatile(
        "mma.sync.aligned.m16n8k16.row.col.f32.f16.f16.f32 "
        "{%0,%1,%2,%3},{%4,%5,%6,%7},{%8,%9},{%0,%1,%2,%3};"
        : "+f"(c[0]), "+f"(c[1]), "+f"(c[2]), "+f"(c[3])
        : "r"(a[0]), "r"(a[1]), "r"(a[2]), "r"(a[3]), "r"(b[0]), "r"(b[1]));
}

__device__ __forceinline__ void ldsm_x4(unsigned r[4], unsigned addr) {
    asm volatile("ldmatrix.sync.aligned.m8n8.x4.shared.b16 {%0,%1,%2,%3}, [%4];"
                 : "=r"(r[0]), "=r"(r[1]), "=r"(r[2]), "=r"(r[3]) : "r"(addr));
}

__device__ __forceinline__ float ex2(float x) {
    float y;
    asm("ex2.approx.f32 %0, %1;" : "=f"(y) : "f"(x));
    return y;
}

__device__ __forceinline__ void cp16(void* dst_smem, const void* src_gmem) {
    unsigned d = (unsigned)__cvta_generic_to_shared(dst_smem);
    asm volatile("cp.async.cg.shared.global [%0], [%1], 16;" :: "r"(d), "l"(src_gmem));
}
#define CP_COMMIT() asm volatile("cp.async.commit_group;")
#define CP_WAIT0()  asm volatile("cp.async.wait_group 0;")

// fp32 -> fp16 elementwise (float4 granularity)
__global__ void f2h_kernel(const float* __restrict__ in, __half* __restrict__ out, int n4) {
    int i = blockIdx.x * blockDim.x + threadIdx.x;
    if (i >= n4) return;
    float4 v = ((const float4*)in)[i];
    ((__half2*)out)[2 * i]     = __floats2half2_rn(v.x, v.y);
    ((__half2*)out)[2 * i + 1] = __floats2half2_rn(v.z, v.w);
}

// out[C][R] (fp16) = in[R][C]^T
__global__ void transpose_h_kernel(const float* __restrict__ in,
                                   __half* __restrict__ out, int R, int C) {
    __shared__ float t[32][33];
    int c0 = blockIdx.x * 32, r0 = blockIdx.y * 32;
    int tx = threadIdx.x, ty = threadIdx.y;
    #pragma unroll
    for (int i = 0; i < 4; i++)
        t[ty + i * 8][tx] = in[(size_t)(r0 + ty + i * 8) * C + c0 + tx];
    __syncthreads();
    #pragma unroll
    for (int i = 0; i < 4; i++)
        out[(size_t)(c0 + ty + i * 8) * R + r0 + tx] = __float2half(t[tx][ty + i * 8]);
}

// ---------------------------------------------------------------------------
// FP16 tensor-core GEMM (R12 winner): C[M,N] = A[M,K] @ BT[N,K]^T + bias.
// BM=BN=128, BK=32. 256 threads = 8 warps (4m x 2n); warp tile 32x64.
// ldmatrix fragment loads.
// ---------------------------------------------------------------------------
#define PHG 40   // smem pitch in halves; 20 words: 20r mod 32 spans all banks

__global__ __launch_bounds__(256) void gemm_h_kernel(
    const __half* __restrict__ A, const __half* __restrict__ BT,
    const float* __restrict__ bias, void* __restrict__ Cout,
    int M, int N, int K, int half_out) {
    __shared__ __half As[128 * PHG];
    __shared__ __half Bs[128 * PHG];

    int tid = threadIdx.x;
    int wid = tid >> 5, lane = tid & 31;
    int g = lane >> 2, tig = lane & 3;
    int warp_m = wid >> 1, warp_n = wid & 1;
    int bm = blockIdx.y * 128, bn = blockIdx.x * 128;

    int lr = tid >> 1, lc = (tid & 1) * 16;
    const __half* Agp = A + (size_t)(bm + lr) * K + lc;
    const __half* Bgp = BT + (size_t)(bn + lr) * K + lc;

    int lm = lane >> 3, lrw = lane & 7;
    unsigned a_addr[2], b_addr[4];
    #pragma unroll
    for (int mc = 0; mc < 2; mc++)
        a_addr[mc] = (unsigned)__cvta_generic_to_shared(
            &As[(warp_m * 32 + mc * 16 + (lm & 1) * 8 + lrw) * PHG + (lm >> 1) * 8]);
    #pragma unroll
    for (int j = 0; j < 4; j++)
        b_addr[j] = (unsigned)__cvta_generic_to_shared(
            &Bs[(warp_n * 64 + j * 16 + (lm >> 1) * 8 + lrw) * PHG + (lm & 1) * 8]);

    float acc[2][8][4];
    #pragma unroll
    for (int mc = 0; mc < 2; mc++)
        #pragma unroll
        for (int nc = 0; nc < 8; nc++)
            #pragma unroll
            for (int i = 0; i < 4; i++) acc[mc][nc][i] = 0.0f;

    for (int k0 = 0; k0 < K; k0 += 32) {
        __syncthreads();
        *(uint4*)&As[lr * PHG + lc]     = *(const uint4*)(Agp + k0);
        *(uint4*)&As[lr * PHG + lc + 8] = *(const uint4*)(Agp + k0 + 8);
        *(uint4*)&Bs[lr * PHG + lc]     = *(const uint4*)(Bgp + k0);
        *(uint4*)&Bs[lr * PHG + lc + 8] = *(const uint4*)(Bgp + k0 + 8);
        __syncthreads();

        #pragma unroll
        for (int kc = 0; kc < 2; kc++) {
            unsigned a[2][4];
            ldsm_x4(a[0], a_addr[0] + kc * 32);
            ldsm_x4(a[1], a_addr[1] + kc * 32);
            #pragma unroll
            for (int j = 0; j < 4; j++) {
                unsigned bb[4];
                ldsm_x4(bb, b_addr[j] + kc * 32);
                mma_f16(acc[0][2 * j],     a[0], bb);
                mma_f16(acc[1][2 * j],     a[1], bb);
                mma_f16(acc[0][2 * j + 1], a[0], bb + 2);
                mma_f16(acc[1][2 * j + 1], a[1], bb + 2);
            }
        }
    }

    // Epilogue
    #pragma unroll
    for (int nc = 0; nc < 8; nc++) {
        int col = bn + warp_n * 64 + nc * 8 + 2 * tig;
        float bv0 = bias[col], bv1 = bias[col + 1];
        #pragma unroll
        for (int mc = 0; mc < 2; mc++) {
            int row = bm + warp_m * 32 + mc * 16 + g;
            float v00 = acc[mc][nc][0] + bv0, v01 = acc[mc][nc][1] + bv1;
            float v10 = acc[mc][nc][2] + bv0, v11 = acc[mc][nc][3] + bv1;
            if (half_out) {
                __half* Ch = (__half*)Cout;
                *(__half2*)&Ch[(size_t)row * N + col]       = __floats2half2_rn(v00, v01);
                *(__half2*)&Ch[(size_t)(row + 8) * N + col] = __floats2half2_rn(v10, v11);
            } else {
                float* Cf = (float*)Cout;
                *(float2*)&Cf[(size_t)row * N + col]       = make_float2(v00, v01);
                *(float2*)&Cf[(size_t)(row + 8) * N + col] = make_float2(v10, v11);
            }
        }
    }
}

// ---------------------------------------------------------------------------
// Flash attention (causal), fp16 m16n8k16 mma, ldmatrix, exp2 softmax.
// One CTA per (q-block 128, head). 256 threads = 8 warps; warp w owns rows
// 16w..16w+15. K/V tiles of 64 kpos (double-buffered), amortized over 128 rows.
// ---------------------------------------------------------------------------
#define PW 36
#define ROWB 144   // bytes per tile row (36 words)
#define BMA 128
#define SCALE2 0.18033688011112042f   // 0.125 * log2(e)

__global__ __launch_bounds__(256) void attn_h_kernel() {
    extern __shared__ unsigned sm[];
    unsigned* Ps = sm;                   // [128 rows][36 words] (kpos pairs)
    unsigned* Ks = Ps + BMA * PW;        // [2][64 kpos][36 words] (hd halves)
    unsigned* Vs = Ks + 2 * 64 * PW;     // [2][64 hd][36 words] (kpos pairs)

    int qb = gridDim.x - 1 - blockIdx.x;  // longest CTAs first
    int h  = blockIdx.y;
    int tid = threadIdx.x;
    int wid = tid >> 5, lane = tid & 31;
    int g = lane >> 2, tig = lane & 3;
    int row0 = wid * 16;

    const int k_off = DMODEL + h * HDIM;
    const int v_off = 2 * DMODEL + h * HDIM;

    unsigned smb = (unsigned)__cvta_generic_to_shared(sm);
    unsigned ps_b = smb;
    unsigned ks_b = smb + BMA * ROWB;
    unsigned vs_b = ks_b + 2 * 64 * ROWB;

    int lm = lane >> 3, lrw = lane & 7;
    unsigned apat = (unsigned)((row0 + (lm & 1) * 8 + lrw) * ROWB + (lm >> 1) * 16);
    unsigned bpat[4];
    #pragma unroll
    for (int j = 0; j < 4; j++)
        bpat[j] = (unsigned)((j * 16 + (lm >> 1) * 8 + lrw) * ROWB + (lm & 1) * 16);

    // K loader: 64 rows x 64 halves = 512 cp16; 2 per thread
    auto cp_k = [&](int jb, int buf) {
        char* Kd = (char*)(Ks + buf * 64 * PW);
        #pragma unroll
        for (int i = 0; i < 2; i++) {
            int linear = tid + i * 256;
            int r  = linear >> 3;
            int c8 = (linear & 7) * 8;
            cp16(Kd + r * ROWB + c8 * 2,
                 &g_qkv_h[(size_t)(jb * 64 + r) * QKV_N + k_off + c8]);
        }
    };

    // V loader: warp wid covers hd [wid*8, +8); lane owns kpos pair (2l, 2l+1)
    int vc0 = wid * 8, vp = lane;
    uint4 vr[2];
    auto v_ldg = [&](int jb) {
        const __half* p0 = &g_qkv_h[(size_t)(jb * 64 + 2 * vp) * QKV_N + v_off + vc0];
        vr[0] = *(const uint4*)p0;
        vr[1] = *(const uint4*)(p0 + QKV_N);
    };
    auto v_sts = [&](int buf) {
        unsigned* Vd = Vs + buf * 64 * PW;
        const __half* r0 = (const __half*)&vr[0];
        const __half* r1 = (const __half*)&vr[1];
        #pragma unroll
        for (int j = 0; j < 8; j++) {
            __half2 w = __halves2half2(r0[j], r1[j]);
            Vd[(vc0 + j) * PW + vp] = *(unsigned*)&w;
        }
    };

    cp_k(0, 0);
    CP_COMMIT();
    v_ldg(0);

    // Q fragments in registers (warp rows qb*128+row0 ..+15)
    unsigned qf[4][4];
    {
        const __half* Qb = g_qkv_h + (size_t)(qb * BMA) * QKV_N + h * HDIM;
        #pragma unroll
        for (int kc = 0; kc < 4; kc++) {
            qf[kc][0] = *(const unsigned*)&Qb[(size_t)(row0 + g) * QKV_N + kc * 16 + 2 * tig];
            qf[kc][1] = *(const unsigned*)&Qb[(size_t)(row0 + g + 8) * QKV_N + kc * 16 + 2 * tig];
            qf[kc][2] = *(const unsigned*)&Qb[(size_t)(row0 + g) * QKV_N + kc * 16 + 2 * tig + 8];
            qf[kc][3] = *(const unsigned*)&Qb[(size_t)(row0 + g + 8) * QKV_N + kc * 16 + 2 * tig + 8];
        }
    }
    v_sts(0);

    float o[8][4];
    #pragma unroll
    for (int nc = 0; nc < 8; nc++)
        #pragma unroll
        for (int i = 0; i < 4; i++) o[nc][i] = 0.0f;
    float m0 = -1e30f, m1 = -1e30f, l0 = 0.0f, l1 = 0.0f;

    int jb_max = 2 * qb + 1;

    for (int jb = 0; jb <= jb_max; jb++) {
        int buf = jb & 1;
        CP_WAIT0();
        __syncthreads();

        if (jb < jb_max) {
            cp_k(jb + 1, buf ^ 1);
            CP_COMMIT();
            v_ldg(jb + 1);
        }

        unsigned kc_b = ks_b + buf * 64 * ROWB;
        unsigned vc_b = vs_b + buf * 64 * ROWB;

        // ---- S = Q @ K^T ----
        float s[8][4];
        #pragma unroll
        for (int nc = 0; nc < 8; nc++)
            #pragma unroll
            for (int i = 0; i < 4; i++) s[nc][i] = 0.0f;

        #pragma unroll
        for (int kc = 0; kc < 4; kc++) {
            #pragma unroll
            for (int j = 0; j < 4; j++) {
                unsigned bb[4];
                ldsm_x4(bb, kc_b + bpat[j] + kc * 32);
                mma_f16(s[2 * j],     qf[kc], bb);
                mma_f16(s[2 * j + 1], qf[kc], bb + 2);
            }
        }

        #pragma unroll
        for (int nc = 0; nc < 8; nc++)
            #pragma unroll
            for (int i = 0; i < 4; i++) s[nc][i] *= SCALE2;

        if (jb >= 2 * qb) {
            int coff = jb * 64 - qb * BMA;   // 0 or 64
            int r_lo = row0 + g, r_hi = row0 + g + 8;
            #pragma unroll
            for (int nc = 0; nc < 8; nc++) {
                int c0 = nc * 8 + 2 * tig + coff, c1 = c0 + 1;
                if (c0 > r_lo) s[nc][0] = -1e30f;
                if (c1 > r_lo) s[nc][1] = -1e30f;
                if (c0 > r_hi) s[nc][2] = -1e30f;
                if (c1 > r_hi) s[nc][3] = -1e30f;
            }
        }

        if (jb < jb_max) v_sts(buf ^ 1);

        float mx0 = -1e30f, mx1 = -1e30f;
        #pragma unroll
        for (int nc = 0; nc < 8; nc++) {
            mx0 = fmaxf(mx0, fmaxf(s[nc][0], s[nc][1]));
            mx1 = fmaxf(mx1, fmaxf(s[nc][2], s[nc][3]));
        }
        mx0 = fmaxf(mx0, __shfl_xor_sync(0xffffffffu, mx0, 1));
        mx0 = fmaxf(mx0, __shfl_xor_sync(0xffffffffu, mx0, 2));
        mx1 = fmaxf(mx1, __shfl_xor_sync(0xffffffffu, mx1, 1));
        mx1 = fmaxf(mx1, __shfl_xor_sync(0xffffffffu, mx1, 2));

        float mn0 = fmaxf(m0, mx0), mn1 = fmaxf(m1, mx1);
        float al0 = ex2(m0 - mn0), al1 = ex2(m1 - mn1);

        float rs0 = 0.0f, rs1 = 0.0f;
        #pragma unroll
        for (int nc = 0; nc < 8; nc++) {
            float p0 = ex2(s[nc][0] - mn0);
            float p1 = ex2(s[nc][1] - mn0);
            float p2 = ex2(s[nc][2] - mn1);
            float p3 = ex2(s[nc][3] - mn1);
            rs0 += p0 + p1;
            rs1 += p2 + p3;
            __half2 lo = __floats2half2_rn(p0, p1);
            __half2 hi = __floats2half2_rn(p2, p3);
            Ps[(row0 + g) * PW + nc * 4 + tig]     = *(unsigned*)&lo;
            Ps[(row0 + g + 8) * PW + nc * 4 + tig] = *(unsigned*)&hi;
        }
        rs0 += __shfl_xor_sync(0xffffffffu, rs0, 1);
        rs0 += __shfl_xor_sync(0xffffffffu, rs0, 2);
        rs1 += __shfl_xor_sync(0xffffffffu, rs1, 1);
        rs1 += __shfl_xor_sync(0xffffffffu, rs1, 2);

        l0 = l0 * al0 + rs0;
        l1 = l1 * al1 + rs1;
        m0 = mn0;
        m1 = mn1;
        #pragma unroll
        for (int nc = 0; nc < 8; nc++) {
            o[nc][0] *= al0; o[nc][1] *= al0;
            o[nc][2] *= al1; o[nc][3] *= al1;
        }
        __syncwarp();   // Ps rows are warp-private

        // ---- O += P @ V ----
        #pragma unroll
        for (int kc = 0; kc < 4; kc++) {
            unsigned a[4];
            ldsm_x4(a, ps_b + apat + kc * 32);
            #pragma unroll
            for (int j = 0; j < 4; j++) {
                unsigned bb[4];
                ldsm_x4(bb, vc_b + bpat[j] + kc * 32);
                mma_f16(o[2 * j],     a, bb);
                mma_f16(o[2 * j + 1], a, bb + 2);
            }
        }
    }

    // Normalize, write ctx (fp16)
    float inv0 = 1.0f / l0, inv1 = 1.0f / l1;
    #pragma unroll
    for (int nc = 0; nc < 8; nc++) {
        int col = h * HDIM + nc * 8 + 2 * tig;
        int r_lo = qb * BMA + row0 + g;
        __half2 lo = __floats2half2_rn(o[nc][0] * inv0, o[nc][1] * inv0);
        __half2 hi = __floats2half2_rn(o[nc][2] * inv1, o[nc][3] * inv1);
        *(__half2*)&g_ctx_h[(size_t)r_lo * DMODEL + col]       = lo;
        *(__half2*)&g_ctx_h[(size_t)(r_lo + 8) * DMODEL + col] = hi;
    }
}

// ---------------------------------------------------------------------------
extern "C" void kernel_launch(void* const* d_in, const int* in_sizes, int n_in,
                              void* d_out, int out_size) {
    (void)in_sizes; (void)n_in; (void)out_size;
    const float* x     = (const float*)d_in[0];
    const float* w_qkv = (const float*)d_in[1];
    const float* b_qkv = (const float*)d_in[2];
    const float* w_out = (const float*)d_in[3];
    const float* b_out = (const float*)d_in[4];
    float* out = (float*)d_out;

    __half *qkv_ptr, *ctx_ptr, *xh_ptr, *wqkvT_ptr, *woutT_ptr;
    cudaGetSymbolAddress((void**)&qkv_ptr,   g_qkv_h);
    cudaGetSymbolAddress((void**)&ctx_ptr,   g_ctx_h);
    cudaGetSymbolAddress((void**)&xh_ptr,    g_x_h);
    cudaGetSymbolAddress((void**)&wqkvT_ptr, g_wqkvT_h);
    cudaGetSymbolAddress((void**)&woutT_ptr, g_woutT_h);

    const int ATTN_SMEM = (BMA + 2 * 64 + 2 * 64) * PW * (int)sizeof(unsigned);  // 55296
    static bool attr_set = false;
    if (!attr_set) {
        cudaFuncSetAttribute(attn_h_kernel,
                             cudaFuncAttributeMaxDynamicSharedMemorySize, ATTN_SMEM);
        attr_set = true;
    }

    // 0) Convert inputs: x -> fp16; weights -> transposed fp16 [N][K]
    f2h_kernel<<<(SEQ * DMODEL / 4 + 255) / 256, 256>>>(x, xh_ptr, SEQ * DMODEL / 4);
    transpose_h_kernel<<<dim3(QKV_N / 32, DMODEL / 32), dim3(32, 8)>>>(
        w_qkv, wqkvT_ptr, DMODEL, QKV_N);
    transpose_h_kernel<<<dim3(DMODEL / 32, DMODEL / 32), dim3(32, 8)>>>(
        w_out, woutT_ptr, DMODEL, DMODEL);

    // 1) QKV projection (fp16 out)
    gemm_h_kernel<<<dim3(QKV_N / 128, SEQ / 128), 256>>>(
        xh_ptr, wqkvT_ptr, b_qkv, qkv_ptr, SEQ, QKV_N, DMODEL, 1);

    // 2) Causal attention
    attn_h_kernel<<<dim3(SEQ / BMA, NHEADS), 256, ATTN_SMEM>>>();

    // 3) Output projection (fp32 out)
    gemm_h_kernel<<<dim3(DMODEL / 128, SEQ / 128), 256>>>(
        ctx_ptr, woutT_ptr, b_out, out, SEQ, DMODEL, DMODEL, 0);
}

// round 15
// speedup vs baseline: 1.1483x; 1.0321x over previous
#include <cuda_runtime.h>
#include <cuda_fp16.h>

#define SEQ 4096
#define DMODEL 1024
#define NHEADS 16
#define HDIM 64
#define QKV_N 3072

// Scratch (static device arrays — no allocation)
__device__ __half g_qkv_h[SEQ * QKV_N];   // q|k|v fp16
__device__ __half g_ctx_h[SEQ * DMODEL];  // ctx fp16
__device__ __half g_x_h[SEQ * DMODEL];            // x fp16
__device__ __half g_wqkvT_h[QKV_N * DMODEL];      // w_qkv^T [N][K] fp16
__device__ __half g_woutT_h[DMODEL * DMODEL];     // w_out^T [N][K] fp16

// ---------------------------------------------------------------------------
// helpers
// ---------------------------------------------------------------------------
__device__ __forceinline__ void mma_f16(float c[4], const unsigned a[4], const unsigned b[2]) {
    asm volatile(
        "mma.sync.aligned.m16n8k16.row.col.f32.f16.f16.f32 "
        "{%0,%1,%2,%3},{%4,%5,%6,%7},{%8,%9},{%0,%1,%2,%3};"
        : "+f"(c[0]), "+f"(c[1]), "+f"(c[2]), "+f"(c[3])
        : "r"(a[0]), "r"(a[1]), "r"(a[2]), "r"(a[3]), "r"(b[0]), "r"(b[1]));
}

__device__ __forceinline__ void ldsm_x4(unsigned r[4], unsigned addr) {
    asm volatile("ldmatrix.sync.aligned.m8n8.x4.shared.b16 {%0,%1,%2,%3}, [%4];"
                 : "=r"(r[0]), "=r"(r[1]), "=r"(r[2]), "=r"(r[3]) : "r"(addr));
}

__device__ __forceinline__ float ex2(float x) {
    float y;
    asm("ex2.approx.f32 %0, %1;" : "=f"(y) : "f"(x));
    return y;
}

__device__ __forceinline__ void cp16(void* dst_smem, const void* src_gmem) {
    unsigned d = (unsigned)__cvta_generic_to_shared(dst_smem);
    asm volatile("cp.async.cg.shared.global [%0], [%1], 16;" :: "r"(d), "l"(src_gmem));
}
#define CP_COMMIT() asm volatile("cp.async.commit_group;")
#define CP_WAIT0()  asm volatile("cp.async.wait_group 0;")

// fp32 -> fp16 elementwise (float4 granularity)
__global__ void f2h_kernel(const float* __restrict__ in, __half* __restrict__ out, int n4) {
    int i = blockIdx.x * blockDim.x + threadIdx.x;
    if (i >= n4) return;
    float4 v = ((const float4*)in)[i];
    ((__half2*)out)[2 * i]     = __floats2half2_rn(v.x, v.y);
    ((__half2*)out)[2 * i + 1] = __floats2half2_rn(v.z, v.w);
}

// out[C][R] (fp16) = in[R][C]^T
__global__ void transpose_h_kernel(const float* __restrict__ in,
                                   __half* __restrict__ out, int R, int C) {
    __shared__ float t[32][33];
    int c0 = blockIdx.x * 32, r0 = blockIdx.y * 32;
    int tx = threadIdx.x, ty = threadIdx.y;
    #pragma unroll
    for (int i = 0; i < 4; i++)
        t[ty + i * 8][tx] = in[(size_t)(r0 + ty + i * 8) * C + c0 + tx];
    __syncthreads();
    #pragma unroll
    for (int i = 0; i < 4; i++)
        out[(size_t)(c0 + ty + i * 8) * R + r0 + tx] = __float2half(t[tx][ty + i * 8]);
}

// ---------------------------------------------------------------------------
// FP16 tensor-core GEMM, cp.async double-buffered, one barrier per k-tile.
// C[M,N] = A[M,K] @ BT[N,K]^T + bias. BM=BN=128, BK=32. 256 threads = 8 warps
// (4m x 2n); warp tile 32x64. ldmatrix fragment loads.
// ---------------------------------------------------------------------------
#define PHG 40   // smem pitch in halves; 20 words: 20r mod 32 spans all banks
#define GSTG (128 * PHG)          // halves per tile per operand
#define GSTGB (GSTG * 2)          // bytes per tile per operand (10240)

__global__ __launch_bounds__(256) void gemm_h_kernel(
    const __half* __restrict__ A, const __half* __restrict__ BT,
    const float* __restrict__ bias, void* __restrict__ Cout,
    int M, int N, int K, int half_out) {
    __shared__ __half As[2][GSTG];
    __shared__ __half Bs[2][GSTG];

    int tid = threadIdx.x;
    int wid = tid >> 5, lane = tid & 31;
    int g = lane >> 2, tig = lane & 3;
    int warp_m = wid >> 1, warp_n = wid & 1;
    int bm = blockIdx.y * 128, bn = blockIdx.x * 128;

    int lr = tid >> 1, lc = (tid & 1) * 16;
    const __half* Agp = A + (size_t)(bm + lr) * K + lc;
    const __half* Bgp = BT + (size_t)(bn + lr) * K + lc;

    auto cp_tile = [&](int buf, int k0) {
        cp16(&As[buf][lr * PHG + lc],     Agp + k0);
        cp16(&As[buf][lr * PHG + lc + 8], Agp + k0 + 8);
        cp16(&Bs[buf][lr * PHG + lc],     Bgp + k0);
        cp16(&Bs[buf][lr * PHG + lc + 8], Bgp + k0 + 8);
    };

    int lm = lane >> 3, lrw = lane & 7;
    unsigned a_addr[2], b_addr[4];
    #pragma unroll
    for (int mc = 0; mc < 2; mc++)
        a_addr[mc] = (unsigned)__cvta_generic_to_shared(
            &As[0][(warp_m * 32 + mc * 16 + (lm & 1) * 8 + lrw) * PHG + (lm >> 1) * 8]);
    #pragma unroll
    for (int j = 0; j < 4; j++)
        b_addr[j] = (unsigned)__cvta_generic_to_shared(
            &Bs[0][(warp_n * 64 + j * 16 + (lm >> 1) * 8 + lrw) * PHG + (lm & 1) * 8]);

    float acc[2][8][4];
    #pragma unroll
    for (int mc = 0; mc < 2; mc++)
        #pragma unroll
        for (int nc = 0; nc < 8; nc++)
            #pragma unroll
            for (int i = 0; i < 4; i++) acc[mc][nc][i] = 0.0f;

    int kt_total = K >> 5;

    cp_tile(0, 0);
    CP_COMMIT();

    for (int kt = 0; kt < kt_total; kt++) {
        CP_WAIT0();          // tile kt landed (this thread's copies)
        __syncthreads();     // all threads' copies visible; prev compute done

        if (kt + 1 < kt_total) {
            cp_tile((kt + 1) & 1, (kt + 1) * 32);   // overlaps with compute below
            CP_COMMIT();
        }

        unsigned off = (unsigned)((kt & 1) * GSTGB);
        #pragma unroll
        for (int kc = 0; kc < 2; kc++) {
            unsigned a[2][4];
            ldsm_x4(a[0], a_addr[0] + off + kc * 32);
            ldsm_x4(a[1], a_addr[1] + off + kc * 32);
            #pragma unroll
            for (int j = 0; j < 4; j++) {
                unsigned bb[4];
                ldsm_x4(bb, b_addr[j] + off + kc * 32);
                mma_f16(acc[0][2 * j],     a[0], bb);
                mma_f16(acc[1][2 * j],     a[1], bb);
                mma_f16(acc[0][2 * j + 1], a[0], bb + 2);
                mma_f16(acc[1][2 * j + 1], a[1], bb + 2);
            }
        }
    }

    // Epilogue
    #pragma unroll
    for (int nc = 0; nc < 8; nc++) {
        int col = bn + warp_n * 64 + nc * 8 + 2 * tig;
        float bv0 = bias[col], bv1 = bias[col + 1];
        #pragma unroll
        for (int mc = 0; mc < 2; mc++) {
            int row = bm + warp_m * 32 + mc * 16 + g;
            float v00 = acc[mc][nc][0] + bv0, v01 = acc[mc][nc][1] + bv1;
            float v10 = acc[mc][nc][2] + bv0, v11 = acc[mc][nc][3] + bv1;
            if (half_out) {
                __half* Ch = (__half*)Cout;
                *(__half2*)&Ch[(size_t)row * N + col]       = __floats2half2_rn(v00, v01);
                *(__half2*)&Ch[(size_t)(row + 8) * N + col] = __floats2half2_rn(v10, v11);
            } else {
                float* Cf = (float*)Cout;
                *(float2*)&Cf[(size_t)row * N + col]       = make_float2(v00, v01);
                *(float2*)&Cf[(size_t)(row + 8) * N + col] = make_float2(v10, v11);
            }
        }
    }
}

// ---------------------------------------------------------------------------
// Flash attention (causal), fp16 m16n8k16 mma, ldmatrix, exp2 softmax.
// One CTA per (q-block 128, head). 256 threads = 8 warps. (R14 — known good)
// ---------------------------------------------------------------------------
#define PW 36
#define ROWB 144   // bytes per tile row (36 words)
#define BMA 128
#define SCALE2 0.18033688011112042f   // 0.125 * log2(e)

__global__ __launch_bounds__(256) void attn_h_kernel() {
    extern __shared__ unsigned sm[];
    unsigned* Ps = sm;                   // [128 rows][36 words] (kpos pairs)
    unsigned* Ks = Ps + BMA * PW;        // [2][64 kpos][36 words] (hd halves)
    unsigned* Vs = Ks + 2 * 64 * PW;     // [2][64 hd][36 words] (kpos pairs)

    int qb = gridDim.x - 1 - blockIdx.x;  // longest CTAs first
    int h  = blockIdx.y;
    int tid = threadIdx.x;
    int wid = tid >> 5, lane = tid & 31;
    int g = lane >> 2, tig = lane & 3;
    int row0 = wid * 16;

    const int k_off = DMODEL + h * HDIM;
    const int v_off = 2 * DMODEL + h * HDIM;

    unsigned smb = (unsigned)__cvta_generic_to_shared(sm);
    unsigned ps_b = smb;
    unsigned ks_b = smb + BMA * ROWB;
    unsigned vs_b = ks_b + 2 * 64 * ROWB;

    int lm = lane >> 3, lrw = lane & 7;
    unsigned apat = (unsigned)((row0 + (lm & 1) * 8 + lrw) * ROWB + (lm >> 1) * 16);
    unsigned bpat[4];
    #pragma unroll
    for (int j = 0; j < 4; j++)
        bpat[j] = (unsigned)((j * 16 + (lm >> 1) * 8 + lrw) * ROWB + (lm & 1) * 16);

    // K loader: 64 rows x 64 halves = 512 cp16; 2 per thread
    auto cp_k = [&](int jb, int buf) {
        char* Kd = (char*)(Ks + buf * 64 * PW);
        #pragma unroll
        for (int i = 0; i < 2; i++) {
            int linear = tid + i * 256;
            int r  = linear >> 3;
            int c8 = (linear & 7) * 8;
            cp16(Kd + r * ROWB + c8 * 2,
                 &g_qkv_h[(size_t)(jb * 64 + r) * QKV_N + k_off + c8]);
        }
    };

    // V loader: warp wid covers hd [wid*8, +8); lane owns kpos pair (2l, 2l+1)
    int vc0 = wid * 8, vp = lane;
    uint4 vr[2];
    auto v_ldg = [&](int jb) {
        const __half* p0 = &g_qkv_h[(size_t)(jb * 64 + 2 * vp) * QKV_N + v_off + vc0];
        vr[0] = *(const uint4*)p0;
        vr[1] = *(const uint4*)(p0 + QKV_N);
    };
    auto v_sts = [&](int buf) {
        unsigned* Vd = Vs + buf * 64 * PW;
        const __half* r0 = (const __half*)&vr[0];
        const __half* r1 = (const __half*)&vr[1];
        #pragma unroll
        for (int j = 0; j < 8; j++) {
            __half2 w = __halves2half2(r0[j], r1[j]);
            Vd[(vc0 + j) * PW + vp] = *(unsigned*)&w;
        }
    };

    cp_k(0, 0);
    CP_COMMIT();
    v_ldg(0);

    unsigned qf[4][4];
    {
        const __half* Qb = g_qkv_h + (size_t)(qb * BMA) * QKV_N + h * HDIM;
        #pragma unroll
        for (int kc = 0; kc < 4; kc++) {
            qf[kc][0] = *(const unsigned*)&Qb[(size_t)(row0 + g) * QKV_N + kc * 16 + 2 * tig];
            qf[kc][1] = *(const unsigned*)&Qb[(size_t)(row0 + g + 8) * QKV_N + kc * 16 + 2 * tig];
            qf[kc][2] = *(const unsigned*)&Qb[(size_t)(row0 + g) * QKV_N + kc * 16 + 2 * tig + 8];
            qf[kc][3] = *(const unsigned*)&Qb[(size_t)(row0 + g + 8) * QKV_N + kc * 16 + 2 * tig + 8];
        }
    }
    v_sts(0);

    float o[8][4];
    #pragma unroll
    for (int nc = 0; nc < 8; nc++)
        #pragma unroll
        for (int i = 0; i < 4; i++) o[nc][i] = 0.0f;
    float m0 = -1e30f, m1 = -1e30f, l0 = 0.0f, l1 = 0.0f;

    int jb_max = 2 * qb + 1;

    for (int jb = 0; jb <= jb_max; jb++) {
        int buf = jb & 1;
        CP_WAIT0();
        __syncthreads();

        if (jb < jb_max) {
            cp_k(jb + 1, buf ^ 1);
            CP_COMMIT();
            v_ldg(jb + 1);
        }

        unsigned kc_b = ks_b + buf * 64 * ROWB;
        unsigned vc_b = vs_b + buf * 64 * ROWB;

        // ---- S = Q @ K^T ----
        float s[8][4];
        #pragma unroll
        for (int nc = 0; nc < 8; nc++)
            #pragma unroll
            for (int i = 0; i < 4; i++) s[nc][i] = 0.0f;

        #pragma unroll
        for (int kc = 0; kc < 4; kc++) {
            #pragma unroll
            for (int j = 0; j < 4; j++) {
                unsigned bb[4];
                ldsm_x4(bb, kc_b + bpat[j] + kc * 32);
                mma_f16(s[2 * j],     qf[kc], bb);
                mma_f16(s[2 * j + 1], qf[kc], bb + 2);
            }
        }

        #pragma unroll
        for (int nc = 0; nc < 8; nc++)
            #pragma unroll
            for (int i = 0; i < 4; i++) s[nc][i] *= SCALE2;

        if (jb >= 2 * qb) {
            int coff = jb * 64 - qb * BMA;   // 0 or 64
            int r_lo = row0 + g, r_hi = row0 + g + 8;
            #pragma unroll
            for (int nc = 0; nc < 8; nc++) {
                int c0 = nc * 8 + 2 * tig + coff, c1 = c0 + 1;
                if (c0 > r_lo) s[nc][0] = -1e30f;
                if (c1 > r_lo) s[nc][1] = -1e30f;
                if (c0 > r_hi) s[nc][2] = -1e30f;
                if (c1 > r_hi) s[nc][3] = -1e30f;
            }
        }

        if (jb < jb_max) v_sts(buf ^ 1);

        float mx0 = -1e30f, mx1 = -1e30f;
        #pragma unroll
        for (int nc = 0; nc < 8; nc++) {
            mx0 = fmaxf(mx0, fmaxf(s[nc][0], s[nc][1]));
            mx1 = fmaxf(mx1, fmaxf(s[nc][2], s[nc][3]));
        }
        mx0 = fmaxf(mx0, __shfl_xor_sync(0xffffffffu, mx0, 1));
        mx0 = fmaxf(mx0, __shfl_xor_sync(0xffffffffu, mx0, 2));
        mx1 = fmaxf(mx1, __shfl_xor_sync(0xffffffffu, mx1, 1));
        mx1 = fmaxf(mx1, __shfl_xor_sync(0xffffffffu, mx1, 2));

        float mn0 = fmaxf(m0, mx0), mn1 = fmaxf(m1, mx1);
        float al0 = ex2(m0 - mn0), al1 = ex2(m1 - mn1);

        float rs0 = 0.0f, rs1 = 0.0f;
        #pragma unroll
        for (int nc = 0; nc < 8; nc++) {
            float p0 = ex2(s[nc][0] - mn0);
            float p1 = ex2(s[nc][1] - mn0);
            float p2 = ex2(s[nc][2] - mn1);
            float p3 = ex2(s[nc][3] - mn1);
            rs0 += p0 + p1;
            rs1 += p2 + p3;
            __half2 lo = __floats2half2_rn(p0, p1);
            __half2 hi = __floats2half2_rn(p2, p3);
            Ps[(row0 + g) * PW + nc * 4 + tig]     = *(unsigned*)&lo;
            Ps[(row0 + g + 8) * PW + nc * 4 + tig] = *(unsigned*)&hi;
        }
        rs0 += __shfl_xor_sync(0xffffffffu, rs0, 1);
        rs0 += __shfl_xor_sync(0xffffffffu, rs0, 2);
        rs1 += __shfl_xor_sync(0xffffffffu, rs1, 1);
        rs1 += __shfl_xor_sync(0xffffffffu, rs1, 2);

        l0 = l0 * al0 + rs0;
        l1 = l1 * al1 + rs1;
        m0 = mn0;
        m1 = mn1;
        #pragma unroll
        for (int nc = 0; nc < 8; nc++) {
            o[nc][0] *= al0; o[nc][1] *= al0;
            o[nc][2] *= al1; o[nc][3] *= al1;
        }
        __syncwarp();   // Ps rows are warp-private

        // ---- O += P @ V ----
        #pragma unroll
        for (int kc = 0; kc < 4; kc++) {
            unsigned a[4];
            ldsm_x4(a, ps_b + apat + kc * 32);
            #pragma unroll
            for (int j = 0; j < 4; j++) {
                unsigned bb[4];
                ldsm_x4(bb, vc_b + bpat[j] + kc * 32);
                mma_f16(o[2 * j],     a, bb);
                mma_f16(o[2 * j + 1], a, bb + 2);
            }
        }
    }

    // Normalize, write ctx (fp16)
    float inv0 = 1.0f / l0, inv1 = 1.0f / l1;
    #pragma unroll
    for (int nc = 0; nc < 8; nc++) {
        int col = h * HDIM + nc * 8 + 2 * tig;
        int r_lo = qb * BMA + row0 + g;
        __half2 lo = __floats2half2_rn(o[nc][0] * inv0, o[nc][1] * inv0);
        __half2 hi = __floats2half2_rn(o[nc][2] * inv1, o[nc][3] * inv1);
        *(__half2*)&g_ctx_h[(size_t)r_lo * DMODEL + col]       = lo;
        *(__half2*)&g_ctx_h[(size_t)(r_lo + 8) * DMODEL + col] = hi;
    }
}

// ---------------------------------------------------------------------------
extern "C" void kernel_launch(void* const* d_in, const int* in_sizes, int n_in,
                              void* d_out, int out_size) {
    (void)in_sizes; (void)n_in; (void)out_size;
    const float* x     = (const float*)d_in[0];
    const float* w_qkv = (const float*)d_in[1];
    const float* b_qkv = (const float*)d_in[2];
    const float* w_out = (const float*)d_in[3];
    const float* b_out = (const float*)d_in[4];
    float* out = (float*)d_out;

    __half *qkv_ptr, *ctx_ptr, *xh_ptr, *wqkvT_ptr, *woutT_ptr;
    cudaGetSymbolAddress((void**)&qkv_ptr,   g_qkv_h);
    cudaGetSymbolAddress((void**)&ctx_ptr,   g_ctx_h);
    cudaGetSymbolAddress((void**)&xh_ptr,    g_x_h);
    cudaGetSymbolAddress((void**)&wqkvT_ptr, g_wqkvT_h);
    cudaGetSymbolAddress((void**)&woutT_ptr, g_woutT_h);

    const int ATTN_SMEM = (BMA + 2 * 64 + 2 * 64) * PW * (int)sizeof(unsigned);  // 55296
    static bool attr_set = false;
    if (!attr_set) {
        cudaFuncSetAttribute(attn_h_kernel,
                             cudaFuncAttributeMaxDynamicSharedMemorySize, ATTN_SMEM);
        attr_set = true;
    }

    // 0) Convert inputs: x -> fp16; weights -> transposed fp16 [N][K]
    f2h_kernel<<<(SEQ * DMODEL / 4 + 255) / 256, 256>>>(x, xh_ptr, SEQ * DMODEL / 4);
    transpose_h_kernel<<<dim3(QKV_N / 32, DMODEL / 32), dim3(32, 8)>>>(
        w_qkv, wqkvT_ptr, DMODEL, QKV_N);
    transpose_h_kernel<<<dim3(DMODEL / 32, DMODEL / 32), dim3(32, 8)>>>(
        w_out, woutT_ptr, DMODEL, DMODEL);

    // 1) QKV projection (fp16 out)
    gemm_h_kernel<<<dim3(QKV_N / 128, SEQ / 128), 256>>>(
        xh_ptr, wqkvT_ptr, b_qkv, qkv_ptr, SEQ, QKV_N, DMODEL, 1);

    // 2) Causal attention
    attn_h_kernel<<<dim3(SEQ / BMA, NHEADS), 256, ATTN_SMEM>>>();

    // 3) Output projection (fp32 out)
    gemm_h_kernel<<<dim3(DMODEL / 128, SEQ / 128), 256>>>(
        ctx_ptr, woutT_ptr, b_out, out, SEQ, DMODEL, DMODEL, 0);
}

// round 16
// speedup vs baseline: 1.1600x; 1.0102x over previous
#include <cuda_runtime.h>
#include <cuda_fp16.h>

#define SEQ 4096
#define DMODEL 1024
#define NHEADS 16
#define HDIM 64
#define QKV_N 3072

// Scratch (static device arrays — no allocation)
__device__ __half g_qkv_h[SEQ * QKV_N];   // q|k|v fp16
__device__ __half g_ctx_h[SEQ * DMODEL];  // ctx fp16
__device__ __half g_x_h[SEQ * DMODEL];            // x fp16
__device__ __half g_wqkvT_h[QKV_N * DMODEL];      // w_qkv^T [N][K] fp16
__device__ __half g_woutT_h[DMODEL * DMODEL];     // w_out^T [N][K] fp16

// ---------------------------------------------------------------------------
// helpers
// ---------------------------------------------------------------------------
__device__ __forceinline__ void mma_f16(float c[4], const unsigned a[4], const unsigned b[2]) {
    asm volatile(
        "mma.sync.aligned.m16n8k16.row.col.f32.f16.f16.f32 "
        "{%0,%1,%2,%3},{%4,%5,%6,%7},{%8,%9},{%0,%1,%2,%3};"
        : "+f"(c[0]), "+f"(c[1]), "+f"(c[2]), "+f"(c[3])
        : "r"(a[0]), "r"(a[1]), "r"(a[2]), "r"(a[3]), "r"(b[0]), "r"(b[1]));
}

__device__ __forceinline__ void ldsm_x4(unsigned r[4], unsigned addr) {
    asm volatile("ldmatrix.sync.aligned.m8n8.x4.shared.b16 {%0,%1,%2,%3}, [%4];"
                 : "=r"(r[0]), "=r"(r[1]), "=r"(r[2]), "=r"(r[3]) : "r"(addr));
}

__device__ __forceinline__ float ex2(float x) {
    float y;
    asm("ex2.approx.f32 %0, %1;" : "=f"(y) : "f"(x));
    return y;
}

__device__ __forceinline__ void cp16(void* dst_smem, const void* src_gmem) {
    unsigned d = (unsigned)__cvta_generic_to_shared(dst_smem);
    asm volatile("cp.async.cg.shared.global [%0], [%1], 16;" :: "r"(d), "l"(src_gmem));
}
__device__ __forceinline__ void cp16s(unsigned dst_smem, const void* src_gmem) {
    asm volatile("cp.async.cg.shared.global [%0], [%1], 16;" :: "r"(dst_smem), "l"(src_gmem));
}
#define CP_COMMIT() asm volatile("cp.async.commit_group;")
#define CP_WAIT0()  asm volatile("cp.async.wait_group 0;")
#define CP_WAIT1()  asm volatile("cp.async.wait_group 1;")

// fp32 -> fp16 elementwise (float4 granularity)
__global__ void f2h_kernel(const float* __restrict__ in, __half* __restrict__ out, int n4) {
    int i = blockIdx.x * blockDim.x + threadIdx.x;
    if (i >= n4) return;
    float4 v = ((const float4*)in)[i];
    ((__half2*)out)[2 * i]     = __floats2half2_rn(v.x, v.y);
    ((__half2*)out)[2 * i + 1] = __floats2half2_rn(v.z, v.w);
}

// out[C][R] (fp16) = in[R][C]^T
__global__ void transpose_h_kernel(const float* __restrict__ in,
                                   __half* __restrict__ out, int R, int C) {
    __shared__ float t[32][33];
    int c0 = blockIdx.x * 32, r0 = blockIdx.y * 32;
    int tx = threadIdx.x, ty = threadIdx.y;
    #pragma unroll
    for (int i = 0; i < 4; i++)
        t[ty + i * 8][tx] = in[(size_t)(r0 + ty + i * 8) * C + c0 + tx];
    __syncthreads();
    #pragma unroll
    for (int i = 0; i < 4; i++)
        out[(size_t)(c0 + ty + i * 8) * R + r0 + tx] = __float2half(t[tx][ty + i * 8]);
}

// ---------------------------------------------------------------------------
// FP16 tensor-core GEMM, cp.async 3-stage pipeline (wait_group 1).
// C[M,N] = A[M,K] @ BT[N,K]^T + bias. BM=BN=128, BK=32. 256 threads = 8 warps
// (4m x 2n); warp tile 32x64. ldmatrix fragment loads. Dynamic smem 60KB.
// ---------------------------------------------------------------------------
#define PHG 40   // smem pitch in halves; 20 words: 20r mod 32 spans all banks
#define GSTG (128 * PHG)          // halves per tile per operand (5120)
#define GTILE (2 * GSTG)          // halves per stage (A then B) = 10240
#define GTILEB (GTILE * 2)        // bytes per stage (20480)
#define GEMM_SMEM (3 * GTILEB)    // 61440

__global__ __launch_bounds__(256) void gemm_h_kernel(
    const __half* __restrict__ A, const __half* __restrict__ BT,
    const float* __restrict__ bias, void* __restrict__ Cout,
    int M, int N, int K, int half_out) {
    extern __shared__ __half smh[];    // [3][ A(5120) | B(5120) ]

    int tid = threadIdx.x;
    int wid = tid >> 5, lane = tid & 31;
    int g = lane >> 2, tig = lane & 3;
    int warp_m = wid >> 1, warp_n = wid & 1;
    int bm = blockIdx.y * 128, bn = blockIdx.x * 128;

    int lr = tid >> 1, lc = (tid & 1) * 16;
    const __half* Agp = A + (size_t)(bm + lr) * K + lc;
    const __half* Bgp = BT + (size_t)(bn + lr) * K + lc;

    unsigned smb = (unsigned)__cvta_generic_to_shared(smh);
    unsigned a_sts = smb + (unsigned)(lr * PHG + lc) * 2;
    unsigned b_sts = a_sts + GSTG * 2;

    auto cp_tile = [&](int stg, int k0) {
        unsigned off = (unsigned)(stg * GTILEB);
        cp16s(a_sts + off,      Agp + k0);
        cp16s(a_sts + off + 16, Agp + k0 + 8);
        cp16s(b_sts + off,      Bgp + k0);
        cp16s(b_sts + off + 16, Bgp + k0 + 8);
    };

    int lm = lane >> 3, lrw = lane & 7;
    unsigned a_addr[2], b_addr[4];
    #pragma unroll
    for (int mc = 0; mc < 2; mc++)
        a_addr[mc] = smb + (unsigned)(
            (warp_m * 32 + mc * 16 + (lm & 1) * 8 + lrw) * PHG + (lm >> 1) * 8) * 2;
    #pragma unroll
    for (int j = 0; j < 4; j++)
        b_addr[j] = smb + (unsigned)(GSTG +
            (warp_n * 64 + j * 16 + (lm >> 1) * 8 + lrw) * PHG + (lm & 1) * 8) * 2;

    float acc[2][8][4];
    #pragma unroll
    for (int mc = 0; mc < 2; mc++)
        #pragma unroll
        for (int nc = 0; nc < 8; nc++)
            #pragma unroll
            for (int i = 0; i < 4; i++) acc[mc][nc][i] = 0.0f;

    int kt_total = K >> 5;   // 32

    cp_tile(0, 0);
    CP_COMMIT();
    cp_tile(1, 32);
    CP_COMMIT();

    for (int kt = 0; kt < kt_total; kt++) {
        CP_WAIT1();          // tile kt complete (one younger group may remain)
        __syncthreads();     // visibility + WAR guard on stage (kt+2)%3

        if (kt + 2 < kt_total) cp_tile((kt + 2) % 3, (kt + 2) * 32);
        CP_COMMIT();         // empty group at tail keeps group count consistent

        unsigned off = (unsigned)((kt % 3) * GTILEB);
        #pragma unroll
        for (int kc = 0; kc < 2; kc++) {
            unsigned a[2][4];
            ldsm_x4(a[0], a_addr[0] + off + kc * 32);
            ldsm_x4(a[1], a_addr[1] + off + kc * 32);
            #pragma unroll
            for (int j = 0; j < 4; j++) {
                unsigned bb[4];
                ldsm_x4(bb, b_addr[j] + off + kc * 32);
                mma_f16(acc[0][2 * j],     a[0], bb);
                mma_f16(acc[1][2 * j],     a[1], bb);
                mma_f16(acc[0][2 * j + 1], a[0], bb + 2);
                mma_f16(acc[1][2 * j + 1], a[1], bb + 2);
            }
        }
    }

    // Epilogue
    #pragma unroll
    for (int nc = 0; nc < 8; nc++) {
        int col = bn + warp_n * 64 + nc * 8 + 2 * tig;
        float bv0 = bias[col], bv1 = bias[col + 1];
        #pragma unroll
        for (int mc = 0; mc < 2; mc++) {
            int row = bm + warp_m * 32 + mc * 16 + g;
            float v00 = acc[mc][nc][0] + bv0, v01 = acc[mc][nc][1] + bv1;
            float v10 = acc[mc][nc][2] + bv0, v11 = acc[mc][nc][3] + bv1;
            if (half_out) {
                __half* Ch = (__half*)Cout;
                *(__half2*)&Ch[(size_t)row * N + col]       = __floats2half2_rn(v00, v01);
                *(__half2*)&Ch[(size_t)(row + 8) * N + col] = __floats2half2_rn(v10, v11);
            } else {
                float* Cf = (float*)Cout;
                *(float2*)&Cf[(size_t)row * N + col]       = make_float2(v00, v01);
                *(float2*)&Cf[(size_t)(row + 8) * N + col] = make_float2(v10, v11);
            }
        }
    }
}

// ---------------------------------------------------------------------------
// Flash attention (causal), fp16 m16n8k16 mma, ldmatrix, exp2 softmax.
// One CTA per (q-block 128, head). 256 threads = 8 warps. (R14/R15 — known good)
// ---------------------------------------------------------------------------
#define PW 36
#define ROWB 144   // bytes per tile row (36 words)
#define BMA 128
#define SCALE2 0.18033688011112042f   // 0.125 * log2(e)

__global__ __launch_bounds__(256) void attn_h_kernel() {
    extern __shared__ unsigned sm[];
    unsigned* Ps = sm;                   // [128 rows][36 words] (kpos pairs)
    unsigned* Ks = Ps + BMA * PW;        // [2][64 kpos][36 words] (hd halves)
    unsigned* Vs = Ks + 2 * 64 * PW;     // [2][64 hd][36 words] (kpos pairs)

    int qb = gridDim.x - 1 - blockIdx.x;  // longest CTAs first
    int h  = blockIdx.y;
    int tid = threadIdx.x;
    int wid = tid >> 5, lane = tid & 31;
    int g = lane >> 2, tig = lane & 3;
    int row0 = wid * 16;

    const int k_off = DMODEL + h * HDIM;
    const int v_off = 2 * DMODEL + h * HDIM;

    unsigned smb = (unsigned)__cvta_generic_to_shared(sm);
    unsigned ps_b = smb;
    unsigned ks_b = smb + BMA * ROWB;
    unsigned vs_b = ks_b + 2 * 64 * ROWB;

    int lm = lane >> 3, lrw = lane & 7;
    unsigned apat = (unsigned)((row0 + (lm & 1) * 8 + lrw) * ROWB + (lm >> 1) * 16);
    unsigned bpat[4];
    #pragma unroll
    for (int j = 0; j < 4; j++)
        bpat[j] = (unsigned)((j * 16 + (lm >> 1) * 8 + lrw) * ROWB + (lm & 1) * 16);

    // K loader: 64 rows x 64 halves = 512 cp16; 2 per thread
    auto cp_k = [&](int jb, int buf) {
        char* Kd = (char*)(Ks + buf * 64 * PW);
        #pragma unroll
        for (int i = 0; i < 2; i++) {
            int linear = tid + i * 256;
            int r  = linear >> 3;
            int c8 = (linear & 7) * 8;
            cp16(Kd + r * ROWB + c8 * 2,
                 &g_qkv_h[(size_t)(jb * 64 + r) * QKV_N + k_off + c8]);
        }
    };

    // V loader: warp wid covers hd [wid*8, +8); lane owns kpos pair (2l, 2l+1)
    int vc0 = wid * 8, vp = lane;
    uint4 vr[2];
    auto v_ldg = [&](int jb) {
        const __half* p0 = &g_qkv_h[(size_t)(jb * 64 + 2 * vp) * QKV_N + v_off + vc0];
        vr[0] = *(const uint4*)p0;
        vr[1] = *(const uint4*)(p0 + QKV_N);
    };
    auto v_sts = [&](int buf) {
        unsigned* Vd = Vs + buf * 64 * PW;
        const __half* r0 = (const __half*)&vr[0];
        const __half* r1 = (const __half*)&vr[1];
        #pragma unroll
        for (int j = 0; j < 8; j++) {
            __half2 w = __halves2half2(r0[j], r1[j]);
            Vd[(vc0 + j) * PW + vp] = *(unsigned*)&w;
        }
    };

    cp_k(0, 0);
    CP_COMMIT();
    v_ldg(0);

    unsigned qf[4][4];
    {
        const __half* Qb = g_qkv_h + (size_t)(qb * BMA) * QKV_N + h * HDIM;
        #pragma unroll
        for (int kc = 0; kc < 4; kc++) {
            qf[kc][0] = *(const unsigned*)&Qb[(size_t)(row0 + g) * QKV_N + kc * 16 + 2 * tig];
            qf[kc][1] = *(const unsigned*)&Qb[(size_t)(row0 + g + 8) * QKV_N + kc * 16 + 2 * tig];
            qf[kc][2] = *(const unsigned*)&Qb[(size_t)(row0 + g) * QKV_N + kc * 16 + 2 * tig + 8];
            qf[kc][3] = *(const unsigned*)&Qb[(size_t)(row0 + g + 8) * QKV_N + kc * 16 + 2 * tig + 8];
        }
    }
    v_sts(0);

    float o[8][4];
    #pragma unroll
    for (int nc = 0; nc < 8; nc++)
        #pragma unroll
        for (int i = 0; i < 4; i++) o[nc][i] = 0.0f;
    float m0 = -1e30f, m1 = -1e30f, l0 = 0.0f, l1 = 0.0f;

    int jb_max = 2 * qb + 1;

    for (int jb = 0; jb <= jb_max; jb++) {
        int buf = jb & 1;
        CP_WAIT0();
        __syncthreads();

        if (jb < jb_max) {
            cp_k(jb + 1, buf ^ 1);
            CP_COMMIT();
            v_ldg(jb + 1);
        }

        unsigned kc_b = ks_b + buf * 64 * ROWB;
        unsigned vc_b = vs_b + buf * 64 * ROWB;

        // ---- S = Q @ K^T ----
        float s[8][4];
        #pragma unroll
        for (int nc = 0; nc < 8; nc++)
            #pragma unroll
            for (int i = 0; i < 4; i++) s[nc][i] = 0.0f;

        #pragma unroll
        for (int kc = 0; kc < 4; kc++) {
            #pragma unroll
            for (int j = 0; j < 4; j++) {
                unsigned bb[4];
                ldsm_x4(bb, kc_b + bpat[j] + kc * 32);
                mma_f16(s[2 * j],     qf[kc], bb);
                mma_f16(s[2 * j + 1], qf[kc], bb + 2);
            }
        }

        #pragma unroll
        for (int nc = 0; nc < 8; nc++)
            #pragma unroll
            for (int i = 0; i < 4; i++) s[nc][i] *= SCALE2;

        if (jb >= 2 * qb) {
            int coff = jb * 64 - qb * BMA;   // 0 or 64
            int r_lo = row0 + g, r_hi = row0 + g + 8;
            #pragma unroll
            for (int nc = 0; nc < 8; nc++) {
                int c0 = nc * 8 + 2 * tig + coff, c1 = c0 + 1;
                if (c0 > r_lo) s[nc][0] = -1e30f;
                if (c1 > r_lo) s[nc][1] = -1e30f;
                if (c0 > r_hi) s[nc][2] = -1e30f;
                if (c1 > r_hi) s[nc][3] = -1e30f;
            }
        }

        if (jb < jb_max) v_sts(buf ^ 1);

        float mx0 = -1e30f, mx1 = -1e30f;
        #pragma unroll
        for (int nc = 0; nc < 8; nc++) {
            mx0 = fmaxf(mx0, fmaxf(s[nc][0], s[nc][1]));
            mx1 = fmaxf(mx1, fmaxf(s[nc][2], s[nc][3]));
        }
        mx0 = fmaxf(mx0, __shfl_xor_sync(0xffffffffu, mx0, 1));
        mx0 = fmaxf(mx0, __shfl_xor_sync(0xffffffffu, mx0, 2));
        mx1 = fmaxf(mx1, __shfl_xor_sync(0xffffffffu, mx1, 1));
        mx1 = fmaxf(mx1, __shfl_xor_sync(0xffffffffu, mx1, 2));

        float mn0 = fmaxf(m0, mx0), mn1 = fmaxf(m1, mx1);
        float al0 = ex2(m0 - mn0), al1 = ex2(m1 - mn1);

        float rs0 = 0.0f, rs1 = 0.0f;
        #pragma unroll
        for (int nc = 0; nc < 8; nc++) {
            float p0 = ex2(s[nc][0] - mn0);
            float p1 = ex2(s[nc][1] - mn0);
            float p2 = ex2(s[nc][2] - mn1);
            float p3 = ex2(s[nc][3] - mn1);
            rs0 += p0 + p1;
            rs1 += p2 + p3;
            __half2 lo = __floats2half2_rn(p0, p1);
            __half2 hi = __floats2half2_rn(p2, p3);
            Ps[(row0 + g) * PW + nc * 4 + tig]     = *(unsigned*)&lo;
            Ps[(row0 + g + 8) * PW + nc * 4 + tig] = *(unsigned*)&hi;
        }
        rs0 += __shfl_xor_sync(0xffffffffu, rs0, 1);
        rs0 += __shfl_xor_sync(0xffffffffu, rs0, 2);
        rs1 += __shfl_xor_sync(0xffffffffu, rs1, 1);
        rs1 += __shfl_xor_sync(0xffffffffu, rs1, 2);

        l0 = l0 * al0 + rs0;
        l1 = l1 * al1 + rs1;
        m0 = mn0;
        m1 = mn1;
        #pragma unroll
        for (int nc = 0; nc < 8; nc++) {
            o[nc][0] *= al0; o[nc][1] *= al0;
            o[nc][2] *= al1; o[nc][3] *= al1;
        }
        __syncwarp();   // Ps rows are warp-private

        // ---- O += P @ V ----
        #pragma unroll
        for (int kc = 0; kc < 4; kc++) {
            unsigned a[4];
            ldsm_x4(a, ps_b + apat + kc * 32);
            #pragma unroll
            for (int j = 0; j < 4; j++) {
                unsigned bb[4];
                ldsm_x4(bb, vc_b + bpat[j] + kc * 32);
                mma_f16(o[2 * j],     a, bb);
                mma_f16(o[2 * j + 1], a, bb + 2);
            }
        }
    }

    // Normalize, write ctx (fp16)
    float inv0 = 1.0f / l0, inv1 = 1.0f / l1;
    #pragma unroll
    for (int nc = 0; nc < 8; nc++) {
        int col = h * HDIM + nc * 8 + 2 * tig;
        int r_lo = qb * BMA + row0 + g;
        __half2 lo = __floats2half2_rn(o[nc][0] * inv0, o[nc][1] * inv0);
        __half2 hi = __floats2half2_rn(o[nc][2] * inv1, o[nc][3] * inv1);
        *(__half2*)&g_ctx_h[(size_t)r_lo * DMODEL + col]       = lo;
        *(__half2*)&g_ctx_h[(size_t)(r_lo + 8) * DMODEL + col] = hi;
    }
}

// ---------------------------------------------------------------------------
extern "C" void kernel_launch(void* const* d_in, const int* in_sizes, int n_in,
                              void* d_out, int out_size) {
    (void)in_sizes; (void)n_in; (void)out_size;
    const float* x     = (const float*)d_in[0];
    const float* w_qkv = (const float*)d_in[1];
    const float* b_qkv = (const float*)d_in[2];
    const float* w_out = (const float*)d_in[3];
    const float* b_out = (const float*)d_in[4];
    float* out = (float*)d_out;

    __half *qkv_ptr, *ctx_ptr, *xh_ptr, *wqkvT_ptr, *woutT_ptr;
    cudaGetSymbolAddress((void**)&qkv_ptr,   g_qkv_h);
    cudaGetSymbolAddress((void**)&ctx_ptr,   g_ctx_h);
    cudaGetSymbolAddress((void**)&xh_ptr,    g_x_h);
    cudaGetSymbolAddress((void**)&wqkvT_ptr, g_wqkvT_h);
    cudaGetSymbolAddress((void**)&woutT_ptr, g_woutT_h);

    const int ATTN_SMEM = (BMA + 2 * 64 + 2 * 64) * PW * (int)sizeof(unsigned);  // 55296
    static bool attr_set = false;
    if (!attr_set) {
        cudaFuncSetAttribute(gemm_h_kernel,
                             cudaFuncAttributeMaxDynamicSharedMemorySize, GEMM_SMEM);
        cudaFuncSetAttribute(attn_h_kernel,
                             cudaFuncAttributeMaxDynamicSharedMemorySize, ATTN_SMEM);
        attr_set = true;
    }

    // 0) Convert inputs: x -> fp16; weights -> transposed fp16 [N][K]
    f2h_kernel<<<(SEQ * DMODEL / 4 + 255) / 256, 256>>>(x, xh_ptr, SEQ * DMODEL / 4);
    transpose_h_kernel<<<dim3(QKV_N / 32, DMODEL / 32), dim3(32, 8)>>>(
        w_qkv, wqkvT_ptr, DMODEL, QKV_N);
    transpose_h_kernel<<<dim3(DMODEL / 32, DMODEL / 32), dim3(32, 8)>>>(
        w_out, woutT_ptr, DMODEL, DMODEL);

    // 1) QKV projection (fp16 out)
    gemm_h_kernel<<<dim3(QKV_N / 128, SEQ / 128), 256, GEMM_SMEM>>>(
        xh_ptr, wqkvT_ptr, b_qkv, qkv_ptr, SEQ, QKV_N, DMODEL, 1);

    // 2) Causal attention
    attn_h_kernel<<<dim3(SEQ / BMA, NHEADS), 256, ATTN_SMEM>>>();

    // 3) Output projection (fp32 out)
    gemm_h_kernel<<<dim3(DMODEL / 128, SEQ / 128), 256, GEMM_SMEM>>>(
        ctx_ptr, woutT_ptr, b_out, out, SEQ, DMODEL, DMODEL, 0);
}

// round 17
// speedup vs baseline: 1.4314x; 1.2340x over previous
#include <cuda_runtime.h>
#include <cuda_fp16.h>

#define SEQ 4096
#define DMODEL 1024
#define NHEADS 16
#define HDIM 64
#define QKV_N 3072

// Scratch (static device arrays — no allocation)
__device__ __half g_qkv_h[SEQ * QKV_N];   // q|k|v fp16
__device__ __half g_ctx_h[SEQ * DMODEL];  // ctx fp16
__device__ __half g_x_h[SEQ * DMODEL];            // x fp16
__device__ __half g_wqkvT_h[QKV_N * DMODEL];      // w_qkv^T [N][K] fp16
__device__ __half g_woutT_h[DMODEL * DMODEL];     // w_out^T [N][K] fp16

// ---------------------------------------------------------------------------
// helpers
// ---------------------------------------------------------------------------
__device__ __forceinline__ void mma_f16(float c[4], const unsigned a[4], const unsigned b[2]) {
    asm volatile(
        "mma.sync.aligned.m16n8k16.row.col.f32.f16.f16.f32 "
        "{%0,%1,%2,%3},{%4,%5,%6,%7},{%8,%9},{%0,%1,%2,%3};"
        : "+f"(c[0]), "+f"(c[1]), "+f"(c[2]), "+f"(c[3])
        : "r"(a[0]), "r"(a[1]), "r"(a[2]), "r"(a[3]), "r"(b[0]), "r"(b[1]));
}

__device__ __forceinline__ void ldsm_x4(unsigned r[4], unsigned addr) {
    asm volatile("ldmatrix.sync.aligned.m8n8.x4.shared.b16 {%0,%1,%2,%3}, [%4];"
                 : "=r"(r[0]), "=r"(r[1]), "=r"(r[2]), "=r"(r[3]) : "r"(addr));
}

__device__ __forceinline__ void ldsm_x4_t(unsigned r[4], unsigned addr) {
    asm volatile("ldmatrix.sync.aligned.m8n8.x4.trans.shared.b16 {%0,%1,%2,%3}, [%4];"
                 : "=r"(r[0]), "=r"(r[1]), "=r"(r[2]), "=r"(r[3]) : "r"(addr));
}

__device__ __forceinline__ float ex2(float x) {
    float y;
    asm("ex2.approx.f32 %0, %1;" : "=f"(y) : "f"(x));
    return y;
}

__device__ __forceinline__ void cp16(void* dst_smem, const void* src_gmem) {
    unsigned d = (unsigned)__cvta_generic_to_shared(dst_smem);
    asm volatile("cp.async.cg.shared.global [%0], [%1], 16;" :: "r"(d), "l"(src_gmem));
}
__device__ __forceinline__ void cp16s(unsigned dst_smem, const void* src_gmem) {
    asm volatile("cp.async.cg.shared.global [%0], [%1], 16;" :: "r"(dst_smem), "l"(src_gmem));
}
#define CP_COMMIT() asm volatile("cp.async.commit_group;")
#define CP_WAIT0()  asm volatile("cp.async.wait_group 0;")
#define CP_WAIT1()  asm volatile("cp.async.wait_group 1;")

// fp32 -> fp16 elementwise (float4 granularity)
__global__ void f2h_kernel(const float* __restrict__ in, __half* __restrict__ out, int n4) {
    int i = blockIdx.x * blockDim.x + threadIdx.x;
    if (i >= n4) return;
    float4 v = ((const float4*)in)[i];
    ((__half2*)out)[2 * i]     = __floats2half2_rn(v.x, v.y);
    ((__half2*)out)[2 * i + 1] = __floats2half2_rn(v.z, v.w);
}

// out[C][R] (fp16) = in[R][C]^T
__global__ void transpose_h_kernel(const float* __restrict__ in,
                                   __half* __restrict__ out, int R, int C) {
    __shared__ float t[32][33];
    int c0 = blockIdx.x * 32, r0 = blockIdx.y * 32;
    int tx = threadIdx.x, ty = threadIdx.y;
    #pragma unroll
    for (int i = 0; i < 4; i++)
        t[ty + i * 8][tx] = in[(size_t)(r0 + ty + i * 8) * C + c0 + tx];
    __syncthreads();
    #pragma unroll
    for (int i = 0; i < 4; i++)
        out[(size_t)(c0 + ty + i * 8) * R + r0 + tx] = __float2half(t[tx][ty + i * 8]);
}

// ---------------------------------------------------------------------------
// FP16 tensor-core GEMM, cp.async 3-stage pipeline (R16 — known good).
// C[M,N] = A[M,K] @ BT[N,K]^T + bias. BM=BN=128, BK=32. 256 threads = 8 warps.
// ---------------------------------------------------------------------------
#define PHG 40
#define GSTG (128 * PHG)
#define GTILE (2 * GSTG)
#define GTILEB (GTILE * 2)
#define GEMM_SMEM (3 * GTILEB)    // 61440

__global__ __launch_bounds__(256) void gemm_h_kernel(
    const __half* __restrict__ A, const __half* __restrict__ BT,
    const float* __restrict__ bias, void* __restrict__ Cout,
    int M, int N, int K, int half_out) {
    extern __shared__ __half smh[];

    int tid = threadIdx.x;
    int wid = tid >> 5, lane = tid & 31;
    int g = lane >> 2, tig = lane & 3;
    int warp_m = wid >> 1, warp_n = wid & 1;
    int bm = blockIdx.y * 128, bn = blockIdx.x * 128;

    int lr = tid >> 1, lc = (tid & 1) * 16;
    const __half* Agp = A + (size_t)(bm + lr) * K + lc;
    const __half* Bgp = BT + (size_t)(bn + lr) * K + lc;

    unsigned smb = (unsigned)__cvta_generic_to_shared(smh);
    unsigned a_sts = smb + (unsigned)(lr * PHG + lc) * 2;
    unsigned b_sts = a_sts + GSTG * 2;

    auto cp_tile = [&](int stg, int k0) {
        unsigned off = (unsigned)(stg * GTILEB);
        cp16s(a_sts + off,      Agp + k0);
        cp16s(a_sts + off + 16, Agp + k0 + 8);
        cp16s(b_sts + off,      Bgp + k0);
        cp16s(b_sts + off + 16, Bgp + k0 + 8);
    };

    int lm = lane >> 3, lrw = lane & 7;
    unsigned a_addr[2], b_addr[4];
    #pragma unroll
    for (int mc = 0; mc < 2; mc++)
        a_addr[mc] = smb + (unsigned)(
            (warp_m * 32 + mc * 16 + (lm & 1) * 8 + lrw) * PHG + (lm >> 1) * 8) * 2;
    #pragma unroll
    for (int j = 0; j < 4; j++)
        b_addr[j] = smb + (unsigned)(GSTG +
            (warp_n * 64 + j * 16 + (lm >> 1) * 8 + lrw) * PHG + (lm & 1) * 8) * 2;

    float acc[2][8][4];
    #pragma unroll
    for (int mc = 0; mc < 2; mc++)
        #pragma unroll
        for (int nc = 0; nc < 8; nc++)
            #pragma unroll
            for (int i = 0; i < 4; i++) acc[mc][nc][i] = 0.0f;

    int kt_total = K >> 5;

    cp_tile(0, 0);
    CP_COMMIT();
    cp_tile(1, 32);
    CP_COMMIT();

    for (int kt = 0; kt < kt_total; kt++) {
        CP_WAIT1();
        __syncthreads();

        if (kt + 2 < kt_total) cp_tile((kt + 2) % 3, (kt + 2) * 32);
        CP_COMMIT();

        unsigned off = (unsigned)((kt % 3) * GTILEB);
        #pragma unroll
        for (int kc = 0; kc < 2; kc++) {
            unsigned a[2][4];
            ldsm_x4(a[0], a_addr[0] + off + kc * 32);
            ldsm_x4(a[1], a_addr[1] + off + kc * 32);
            #pragma unroll
            for (int j = 0; j < 4; j++) {
                unsigned bb[4];
                ldsm_x4(bb, b_addr[j] + off + kc * 32);
                mma_f16(acc[0][2 * j],     a[0], bb);
                mma_f16(acc[1][2 * j],     a[1], bb);
                mma_f16(acc[0][2 * j + 1], a[0], bb + 2);
                mma_f16(acc[1][2 * j + 1], a[1], bb + 2);
            }
        }
    }

    #pragma unroll
    for (int nc = 0; nc < 8; nc++) {
        int col = bn + warp_n * 64 + nc * 8 + 2 * tig;
        float bv0 = bias[col], bv1 = bias[col + 1];
        #pragma unroll
        for (int mc = 0; mc < 2; mc++) {
            int row = bm + warp_m * 32 + mc * 16 + g;
            float v00 = acc[mc][nc][0] + bv0, v01 = acc[mc][nc][1] + bv1;
            float v10 = acc[mc][nc][2] + bv0, v11 = acc[mc][nc][3] + bv1;
            if (half_out) {
                __half* Ch = (__half*)Cout;
                *(__half2*)&Ch[(size_t)row * N + col]       = __floats2half2_rn(v00, v01);
                *(__half2*)&Ch[(size_t)(row + 8) * N + col] = __floats2half2_rn(v10, v11);
            } else {
                float* Cf = (float*)Cout;
                *(float2*)&Cf[(size_t)row * N + col]       = make_float2(v00, v01);
                *(float2*)&Cf[(size_t)(row + 8) * N + col] = make_float2(v10, v11);
            }
        }
    }
}

// ---------------------------------------------------------------------------
// Flash attention (causal), fp16 mma. P held in registers (C-layout == A-layout);
// V loaded raw [kpos][hd] via cp.async, fragments via ldmatrix.trans.
// One CTA per (q-block 128, head). 256 threads = 8 warps.
// ---------------------------------------------------------------------------
#define PW 36
#define ROWB 144
#define BMA 128
#define SCALE2 0.18033688011112042f   // 0.125 * log2(e)

__global__ __launch_bounds__(256) void attn_h_kernel() {
    extern __shared__ unsigned sm[];
    unsigned* Ks = sm;                   // [2][64 kpos][36 words]
    unsigned* Vs = Ks + 2 * 64 * PW;     // [2][64 kpos][36 words]

    int qb = gridDim.x - 1 - blockIdx.x;  // longest CTAs first
    int h  = blockIdx.y;
    int tid = threadIdx.x;
    int wid = tid >> 5, lane = tid & 31;
    int g = lane >> 2, tig = lane & 3;
    int row0 = wid * 16;

    const int k_off = DMODEL + h * HDIM;
    const int v_off = 2 * DMODEL + h * HDIM;

    unsigned smb = (unsigned)__cvta_generic_to_shared(sm);
    unsigned ks_b = smb;
    unsigned vs_b = smb + 2 * 64 * ROWB;

    int lm = lane >> 3, lrw = lane & 7;
    // K B-frag pattern (non-trans): rows = kpos (n), cols = hd (k)
    unsigned bpat[4];
    #pragma unroll
    for (int j = 0; j < 4; j++)
        bpat[j] = (unsigned)((j * 16 + (lm >> 1) * 8 + lrw) * ROWB + (lm & 1) * 16);
    // V B-frag pattern (trans): rows = kpos (k), cols = hd (n)
    unsigned vpat[4];
    #pragma unroll
    for (int j = 0; j < 4; j++)
        vpat[j] = (unsigned)(((lm & 1) * 8 + lrw) * ROWB + (j * 16 + (lm >> 1) * 8) * 2);

    // K/V loader: each tile 64 rows x 64 halves; 2 cp16 per thread per tensor
    auto cp_kv = [&](int jb, int buf) {
        unsigned Kd = ks_b + (unsigned)(buf * 64 * ROWB);
        unsigned Vd = vs_b + (unsigned)(buf * 64 * ROWB);
        #pragma unroll
        for (int i = 0; i < 2; i++) {
            int linear = tid + i * 256;
            int r  = linear >> 3;
            int c8 = (linear & 7) * 8;
            size_t grow = (size_t)(jb * 64 + r) * QKV_N;
            cp16s(Kd + r * ROWB + c8 * 2, &g_qkv_h[grow + k_off + c8]);
            cp16s(Vd + r * ROWB + c8 * 2, &g_qkv_h[grow + v_off + c8]);
        }
    };

    cp_kv(0, 0);
    CP_COMMIT();

    // Q fragments in registers
    unsigned qf[4][4];
    {
        const __half* Qb = g_qkv_h + (size_t)(qb * BMA) * QKV_N + h * HDIM;
        #pragma unroll
        for (int kc = 0; kc < 4; kc++) {
            qf[kc][0] = *(const unsigned*)&Qb[(size_t)(row0 + g) * QKV_N + kc * 16 + 2 * tig];
            qf[kc][1] = *(const unsigned*)&Qb[(size_t)(row0 + g + 8) * QKV_N + kc * 16 + 2 * tig];
            qf[kc][2] = *(const unsigned*)&Qb[(size_t)(row0 + g) * QKV_N + kc * 16 + 2 * tig + 8];
            qf[kc][3] = *(const unsigned*)&Qb[(size_t)(row0 + g + 8) * QKV_N + kc * 16 + 2 * tig + 8];
        }
    }

    float o[8][4];
    #pragma unroll
    for (int nc = 0; nc < 8; nc++)
        #pragma unroll
        for (int i = 0; i < 4; i++) o[nc][i] = 0.0f;
    float m0 = -1e30f, m1 = -1e30f, l0 = 0.0f, l1 = 0.0f;

    int jb_max = 2 * qb + 1;

    for (int jb = 0; jb <= jb_max; jb++) {
        int buf = jb & 1;
        CP_WAIT0();
        __syncthreads();

        if (jb < jb_max) {
            cp_kv(jb + 1, buf ^ 1);
            CP_COMMIT();
        }

        unsigned kc_b = ks_b + (unsigned)(buf * 64 * ROWB);
        unsigned vc_b = vs_b + (unsigned)(buf * 64 * ROWB);

        // ---- S = Q @ K^T ----
        float s[8][4];
        #pragma unroll
        for (int nc = 0; nc < 8; nc++)
            #pragma unroll
            for (int i = 0; i < 4; i++) s[nc][i] = 0.0f;

        #pragma unroll
        for (int kc = 0; kc < 4; kc++) {
            #pragma unroll
            for (int j = 0; j < 4; j++) {
                unsigned bb[4];
                ldsm_x4(bb, kc_b + bpat[j] + kc * 32);
                mma_f16(s[2 * j],     qf[kc], bb);
                mma_f16(s[2 * j + 1], qf[kc], bb + 2);
            }
        }

        #pragma unroll
        for (int nc = 0; nc < 8; nc++)
            #pragma unroll
            for (int i = 0; i < 4; i++) s[nc][i] *= SCALE2;

        if (jb >= 2 * qb) {
            int coff = jb * 64 - qb * BMA;   // 0 or 64
            int r_lo = row0 + g, r_hi = row0 + g + 8;
            #pragma unroll
            for (int nc = 0; nc < 8; nc++) {
                int c0 = nc * 8 + 2 * tig + coff, c1 = c0 + 1;
                if (c0 > r_lo) s[nc][0] = -1e30f;
                if (c1 > r_lo) s[nc][1] = -1e30f;
                if (c0 > r_hi) s[nc][2] = -1e30f;
                if (c1 > r_hi) s[nc][3] = -1e30f;
            }
        }

        float mx0 = -1e30f, mx1 = -1e30f;
        #pragma unroll
        for (int nc = 0; nc < 8; nc++) {
            mx0 = fmaxf(mx0, fmaxf(s[nc][0], s[nc][1]));
            mx1 = fmaxf(mx1, fmaxf(s[nc][2], s[nc][3]));
        }
        mx0 = fmaxf(mx0, __shfl_xor_sync(0xffffffffu, mx0, 1));
        mx0 = fmaxf(mx0, __shfl_xor_sync(0xffffffffu, mx0, 2));
        mx1 = fmaxf(mx1, __shfl_xor_sync(0xffffffffu, mx1, 1));
        mx1 = fmaxf(mx1, __shfl_xor_sync(0xffffffffu, mx1, 2));

        float mn0 = fmaxf(m0, mx0), mn1 = fmaxf(m1, mx1);
        float al0 = ex2(m0 - mn0), al1 = ex2(m1 - mn1);

        // P stays in registers: ph[nc] = {half2(p0,p1) row g, half2(p2,p3) row g+8}
        unsigned ph[8][2];
        float rs0 = 0.0f, rs1 = 0.0f;
        #pragma unroll
        for (int nc = 0; nc < 8; nc++) {
            float p0 = ex2(s[nc][0] - mn0);
            float p1 = ex2(s[nc][1] - mn0);
            float p2 = ex2(s[nc][2] - mn1);
            float p3 = ex2(s[nc][3] - mn1);
            rs0 += p0 + p1;
            rs1 += p2 + p3;
            __half2 lo = __floats2half2_rn(p0, p1);
            __half2 hi = __floats2half2_rn(p2, p3);
            ph[nc][0] = *(unsigned*)&lo;
            ph[nc][1] = *(unsigned*)&hi;
        }
        rs0 += __shfl_xor_sync(0xffffffffu, rs0, 1);
        rs0 += __shfl_xor_sync(0xffffffffu, rs0, 2);
        rs1 += __shfl_xor_sync(0xffffffffu, rs1, 1);
        rs1 += __shfl_xor_sync(0xffffffffu, rs1, 2);

        l0 = l0 * al0 + rs0;
        l1 = l1 * al1 + rs1;
        m0 = mn0;
        m1 = mn1;
        #pragma unroll
        for (int nc = 0; nc < 8; nc++) {
            o[nc][0] *= al0; o[nc][1] *= al0;
            o[nc][2] *= al1; o[nc][3] *= al1;
        }

        // ---- O += P @ V (A-frags from registers, B-frags via ldmatrix.trans) ----
        #pragma unroll
        for (int kc = 0; kc < 4; kc++) {
            unsigned a[4] = { ph[2 * kc][0], ph[2 * kc][1],
                              ph[2 * kc + 1][0], ph[2 * kc + 1][1] };
            #pragma unroll
            for (int j = 0; j < 4; j++) {
                unsigned bb[4];
                ldsm_x4_t(bb, vc_b + vpat[j] + kc * 16 * ROWB);
                mma_f16(o[2 * j],     a, bb);
                mma_f16(o[2 * j + 1], a, bb + 2);
            }
        }
    }

    // Normalize, write ctx (fp16)
    float inv0 = 1.0f / l0, inv1 = 1.0f / l1;
    #pragma unroll
    for (int nc = 0; nc < 8; nc++) {
        int col = h * HDIM + nc * 8 + 2 * tig;
        int r_lo = qb * BMA + row0 + g;
        __half2 lo = __floats2half2_rn(o[nc][0] * inv0, o[nc][1] * inv0);
        __half2 hi = __floats2half2_rn(o[nc][2] * inv1, o[nc][3] * inv1);
        *(__half2*)&g_ctx_h[(size_t)r_lo * DMODEL + col]       = lo;
        *(__half2*)&g_ctx_h[(size_t)(r_lo + 8) * DMODEL + col] = hi;
    }
}

// ---------------------------------------------------------------------------
extern "C" void kernel_launch(void* const* d_in, const int* in_sizes, int n_in,
                              void* d_out, int out_size) {
    (void)in_sizes; (void)n_in; (void)out_size;
    const float* x     = (const float*)d_in[0];
    const float* w_qkv = (const float*)d_in[1];
    const float* b_qkv = (const float*)d_in[2];
    const float* w_out = (const float*)d_in[3];
    const float* b_out = (const float*)d_in[4];
    float* out = (float*)d_out;

    __half *qkv_ptr, *ctx_ptr, *xh_ptr, *wqkvT_ptr, *woutT_ptr;
    cudaGetSymbolAddress((void**)&qkv_ptr,   g_qkv_h);
    cudaGetSymbolAddress((void**)&ctx_ptr,   g_ctx_h);
    cudaGetSymbolAddress((void**)&xh_ptr,    g_x_h);
    cudaGetSymbolAddress((void**)&wqkvT_ptr, g_wqkvT_h);
    cudaGetSymbolAddress((void**)&woutT_ptr, g_woutT_h);

    const int ATTN_SMEM = 4 * 64 * PW * (int)sizeof(unsigned);   // 36864
    static bool attr_set = false;
    if (!attr_set) {
        cudaFuncSetAttribute(gemm_h_kernel,
                             cudaFuncAttributeMaxDynamicSharedMemorySize, GEMM_SMEM);
        cudaFuncSetAttribute(attn_h_kernel,
                             cudaFuncAttributeMaxDynamicSharedMemorySize, ATTN_SMEM);
        attr_set = true;
    }

    // 0) Convert inputs: x -> fp16; weights -> transposed fp16 [N][K]
    f2h_kernel<<<(SEQ * DMODEL / 4 + 255) / 256, 256>>>(x, xh_ptr, SEQ * DMODEL / 4);
    transpose_h_kernel<<<dim3(QKV_N / 32, DMODEL / 32), dim3(32, 8)>>>(
        w_qkv, wqkvT_ptr, DMODEL, QKV_N);
    transpose_h_kernel<<<dim3(DMODEL / 32, DMODEL / 32), dim3(32, 8)>>>(
        w_out, woutT_ptr, DMODEL, DMODEL);

    // 1) QKV projection (fp16 out)
    gemm_h_kernel<<<dim3(QKV_N / 128, SEQ / 128), 256, GEMM_SMEM>>>(
        xh_ptr, wqkvT_ptr, b_qkv, qkv_ptr, SEQ, QKV_N, DMODEL, 1);

    // 2) Causal attention
    attn_h_kernel<<<dim3(SEQ / BMA, NHEADS), 256, ATTN_SMEM>>>();

    // 3) Output projection (fp32 out)
    gemm_h_kernel<<<dim3(DMODEL / 128, SEQ / 128), 256, GEMM_SMEM>>>(
        ctx_ptr, woutT_ptr, b_out, out, SEQ, DMODEL, DMODEL, 0);
}